// round 15
// baseline (speedup 1.0000x reference)
#include <cuda_runtime.h>
#include <cuda_bf16.h>
#include <cuda_fp16.h>
#include <cstdint>
#include <cstdio>
#include <math.h>

#define B_  16
#define N_  1024
#define C_  768
#define NH  12
#define HD_ 64
#define QC  2496   // 3*768 + 3*64
#define XC  832    // 768 + 64
#define M1_INV (1.0f/12582912.0f)
#define M2_INV (1.0f/1048576.0f)
#define LR_ 0.001f

// ---------------- scratch ----------------
__device__ float g_qkv[B_*N_*QC];
__device__ float g_gw_part[2*NH*128*HD_*HD_];
__device__ float g_gw_stage[24*8*HD_*HD_];
__device__ float g_gw[2*NH*HD_*HD_];
__device__ float g_gw3_part[B_*64*9];
__device__ float g_gw3[64*9];
__device__ float g_sumsq[25];
__device__ float g_mw1[NH*HD_*HD_];
__device__ float g_mw2[NH*HD_*HD_];
__device__ float g_mw3[64*9];
// fp16 operands (plain fp16, no splits)
__device__ __half g_xh[B_*N_*C_];
__device__ __half g_xch[B_*N_*XC];
__device__ __half g_wqh[QC*C_];   // [N=2496][K=768]
__device__ __half g_wph[C_*XC];   // [N=768][K=832]

// ---------------- PTX helpers ----------------
__device__ __forceinline__ unsigned int smem_to_u32(const void* smem_ptr) {
    unsigned int addr;
    asm("{ .reg .u64 tmp; cvta.to.shared.u64 tmp, %1; cvt.u32.u64 %0, tmp; }"
        : "=r"(addr) : "l"(smem_ptr));
    return addr;
}
__device__ __forceinline__ void cp_async16(unsigned int saddr, const void* gaddr) {
    asm volatile("cp.async.cg.shared.global [%0], [%1], 16;"
                 :: "r"(saddr), "l"(gaddr) : "memory");
}
__device__ __forceinline__ void cp_commit() {
    asm volatile("cp.async.commit_group;" ::: "memory");
}
__device__ __forceinline__ void cp_wait1() {
    asm volatile("cp.async.wait_group 1;" ::: "memory");
}
__device__ __forceinline__ void cp_wait0() {
    asm volatile("cp.async.wait_group 0;" ::: "memory");
}
__device__ __forceinline__ void ldm_x4(unsigned int& r0, unsigned int& r1,
                                       unsigned int& r2, unsigned int& r3,
                                       unsigned int a) {
    asm volatile("ldmatrix.sync.aligned.m8n8.x4.shared.b16 {%0,%1,%2,%3}, [%4];"
                 : "=r"(r0), "=r"(r1), "=r"(r2), "=r"(r3) : "r"(a));
}
__device__ __forceinline__ void ldm_x4t(unsigned int& r0, unsigned int& r1,
                                        unsigned int& r2, unsigned int& r3,
                                        unsigned int a) {
    asm volatile("ldmatrix.sync.aligned.m8n8.x4.trans.shared.b16 {%0,%1,%2,%3}, [%4];"
                 : "=r"(r0), "=r"(r1), "=r"(r2), "=r"(r3) : "r"(a));
}
__device__ __forceinline__ void mma_f16(float& c0, float& c1, float& c2, float& c3,
                                        unsigned int a0, unsigned int a1,
                                        unsigned int a2, unsigned int a3,
                                        unsigned int b0, unsigned int b1) {
    asm volatile("mma.sync.aligned.m16n8k16.row.col.f32.f16.f16.f32 "
                 "{%0,%1,%2,%3}, {%4,%5,%6,%7}, {%8,%9}, {%0,%1,%2,%3};"
                 : "+f"(c0), "+f"(c1), "+f"(c2), "+f"(c3)
                 : "r"(a0), "r"(a1), "r"(a2), "r"(a3), "r"(b0), "r"(b1));
}

// ---------------- conversions ----------------
__device__ __forceinline__ unsigned int pack_h2(__half a, __half b) {
    return (unsigned int)__half_as_ushort(a) |
           ((unsigned int)__half_as_ushort(b) << 16);
}
__global__ __launch_bounds__(256) void convert_f16(
    const float* __restrict__ X, __half* __restrict__ H, int n4)
{
    int i = blockIdx.x * 256 + threadIdx.x;
    if (i >= n4) return;
    float4 v = ((const float4*)X)[i];
    uint2 hh;
    hh.x = pack_h2(__float2half(v.x), __float2half(v.y));
    hh.y = pack_h2(__float2half(v.z), __float2half(v.w));
    ((uint2*)H)[i] = hh;
}
// W[K][N] -> T[N][K] fp16 (no split)
__global__ __launch_bounds__(256) void transpose_f16(
    const float* __restrict__ W, __half* __restrict__ Th, int K, int N)
{
    __shared__ float s[32][33];
    const int n0 = blockIdx.x * 32, k0 = blockIdx.y * 32;
    const int tx = threadIdx.x & 31, ty = threadIdx.x >> 5;
    for (int r = ty; r < 32; r += 8)
        s[r][tx] = W[(size_t)(k0 + r) * N + n0 + tx];
    __syncthreads();
    for (int r = ty; r < 32; r += 8)
        Th[(size_t)(n0 + r) * K + k0 + tx] = __float2half(s[tx][r]);
}

// ---------------- HMMA GEMM (plain fp16, 4 warps x 64x64 tiles, BK=64) --------
#define SROW   72
#define ARR_B  (128*SROW*2)       // 18432 bytes per array
#define STG_B  (2*ARR_B)          // 36864 bytes per stage
#define TCG_SMEM (2*STG_B)        // 73728

__global__ __launch_bounds__(128) void tc_gemm(
    const __half* __restrict__ Ah, const __half* __restrict__ Bh,
    const float* __restrict__ bias, float* __restrict__ C,
    int Nfull, int K)
{
    extern __shared__ __half smb[];
    const unsigned int smem_u = smem_to_u32(smb);
    const int t = threadIdx.x, lane = t & 31, wid = t >> 5;    // 4 warps
    const int m0 = blockIdx.y * 128, n0 = blockIdx.x * 128;
    const int wm = (wid >> 1) * 64, wn = (wid & 1) * 64;

    float acc[4][8][4];
#pragma unroll
    for (int a = 0; a < 4; a++)
#pragma unroll
        for (int b = 0; b < 8; b++)
#pragma unroll
            for (int c = 0; c < 4; c++) acc[a][b][c] = 0.f;

    // load plan: thread t fills row t (64 halves = 8 chunks) of A and of B
    const bool vB = (n0 + t) < Nfull;
    const size_t offA = (size_t)(m0 + t) * K;
    const size_t offB = (size_t)(vB ? (n0 + t) : 0) * K;
    const unsigned int srow = (unsigned int)(t * SROW * 2);

#define ISSUE(stg, ks) do {                                                  \
        unsigned int _sb = smem_u + (unsigned int)(stg) * STG_B + srow;      \
        const int _ko = (ks) * 64;                                           \
        _Pragma("unroll")                                                    \
        for (int c = 0; c < 8; c++) {                                        \
            cp_async16(_sb + c * 16,         Ah + offA + _ko + c * 8);       \
            if (vB)                                                          \
                cp_async16(_sb + ARR_B + c * 16, Bh + offB + _ko + c * 8);   \
        }                                                                    \
        cp_commit();                                                         \
    } while (0)

    const int nk = K / 64;
    ISSUE(0, 0);

    for (int s = 0; s < nk; s++) {
        if (s + 1 < nk) { ISSUE((s + 1) & 1, s + 1); cp_wait1(); }
        else            { cp_wait0(); }
        __syncthreads();

        const unsigned int sb = smem_u + (unsigned int)(s & 1) * STG_B;
#pragma unroll
        for (int kc = 0; kc < 64; kc += 16) {
            // B fragments: 8 n-tiles via 4 ldm_x4
            unsigned int bh[8][2];
#pragma unroll
            for (int q = 0; q < 4; q++) {
                unsigned int brow = (unsigned int)(wn + q * 16 + (lane & 7) +
                                                   ((lane >> 4) << 3));
                unsigned int koff = (unsigned int)(((lane >> 3) & 1) * 8);
                unsigned int ab = sb + 1u * ARR_B + (brow * SROW + kc + koff) * 2;
                ldm_x4(bh[2*q][0], bh[2*q][1], bh[2*q+1][0], bh[2*q+1][1], ab);
            }
#pragma unroll
            for (int mt = 0; mt < 4; mt++) {
                unsigned int arow = (unsigned int)(wm + mt * 16 + (lane & 15));
                unsigned int koff = (unsigned int)((lane >> 4) * 8);
                unsigned int aa = sb + (arow * SROW + kc + koff) * 2;
                unsigned int a0, a1, a2, a3;
                ldm_x4(a0, a1, a2, a3, aa);
#pragma unroll
                for (int nt = 0; nt < 8; nt++)
                    mma_f16(acc[mt][nt][0], acc[mt][nt][1],
                            acc[mt][nt][2], acc[mt][nt][3],
                            a0, a1, a2, a3, bh[nt][0], bh[nt][1]);
            }
        }
        __syncthreads();
    }
#undef ISSUE

    const int g = lane >> 2, tq = lane & 3;
#pragma unroll
    for (int mt = 0; mt < 4; mt++) {
        const int row = m0 + wm + mt * 16 + g;
#pragma unroll
        for (int nt = 0; nt < 8; nt++) {
            const int col = n0 + wn + nt * 8 + tq * 2;
            if (col < Nfull) {
                float b0 = bias[col], b1 = bias[col + 1];
                float2 o1; o1.x = acc[mt][nt][0] + b0; o1.y = acc[mt][nt][1] + b1;
                float2 o2v; o2v.x = acc[mt][nt][2] + b0; o2v.y = acc[mt][nt][3] + b1;
                *(float2*)(C + (size_t)row * Nfull + col) = o1;
                *(float2*)(C + (size_t)(row + 8) * Nfull + col) = o2v;
            }
        }
    }
}

// ---------------- TTT gradient kernel — HMMA (unchanged) ----------------
#define TG_SMEM 73728
__global__ __launch_bounds__(256) void ttt_grad_kernel(
    const float* __restrict__ w1g, const float* __restrict__ w2g)
{
    extern __shared__ __half smh[];
    const unsigned int su  = smem_to_u32(smh);
    const unsigned int w1u = su;
    const unsigned int w2u = su + 4608u * 2;
    const unsigned int k1u = su + 9216u * 2;
    const unsigned int gAu = k1u + 9216u * 2;
    const unsigned int gBu = gAu + 9216u * 2;
    __half* w1T = smh;
    __half* w2T = smh + 4608;
    __half* k1h = smh + 9216;
    __half* gAh = smh + 9216 + 9216;
    __half* gBh = gAh + 9216;

    const int tid = threadIdx.x, lane = tid & 31, wid = tid >> 5;
    const int chunk = blockIdx.x, head = blockIdx.y, b = blockIdx.z;
    const int n0 = chunk * 128;

    for (int idx = tid; idx < 4096; idx += 256) {
        const int k = idx >> 6, n = idx & 63;
        w1T[n * 72 + k] = __float2half(w1g[head * 4096 + idx]);
        w2T[n * 72 + k] = __float2half(w2g[head * 4096 + idx]);
    }
    {
        const float* src = g_qkv + (size_t)(b * N_ + n0) * QC + C_ + head * HD_;
        const int row = tid >> 1, c8 = (tid & 1) * 32;
#pragma unroll
        for (int c = 0; c < 32; c += 4) {
            float4 v = *(const float4*)(src + (size_t)row * QC + c8 + c);
            *(__half2*)&k1h[row * 72 + c8 + c]     = __floats2half2_rn(v.x, v.y);
            *(__half2*)&k1h[row * 72 + c8 + c + 2] = __floats2half2_rn(v.z, v.w);
        }
    }
    __syncthreads();

    const int m0w = wid * 16;
    float accA[8][4], accB[8][4];
#pragma unroll
    for (int nt = 0; nt < 8; nt++)
#pragma unroll
        for (int c = 0; c < 4; c++) { accA[nt][c] = 0.f; accB[nt][c] = 0.f; }

#pragma unroll
    for (int kk = 0; kk < 4; kk++) {
        const unsigned int ak = (unsigned int)(kk * 16 + ((lane >> 4) << 3));
        const unsigned int aa = k1u + ((unsigned int)(m0w + (lane & 15)) * 72 + ak) * 2;
        unsigned int a0, a1, a2, a3;
        ldm_x4(a0, a1, a2, a3, aa);
        unsigned int b1[8][2], b2[8][2];
#pragma unroll
        for (int q = 0; q < 4; q++) {
            const unsigned int brow = (unsigned int)(q * 16 + (lane & 7) +
                                                     ((lane >> 4) << 3));
            const unsigned int bk = (unsigned int)(kk * 16 + ((lane >> 3) & 1) * 8);
            ldm_x4(b1[2*q][0], b1[2*q][1], b1[2*q+1][0], b1[2*q+1][1],
                   w1u + (brow * 72 + bk) * 2);
            ldm_x4(b2[2*q][0], b2[2*q][1], b2[2*q+1][0], b2[2*q+1][1],
                   w2u + (brow * 72 + bk) * 2);
        }
#pragma unroll
        for (int nt = 0; nt < 8; nt++) {
            mma_f16(accA[nt][0], accA[nt][1], accA[nt][2], accA[nt][3],
                    a0, a1, a2, a3, b1[nt][0], b1[nt][1]);
            mma_f16(accB[nt][0], accB[nt][1], accB[nt][2], accB[nt][3],
                    a0, a1, a2, a3, b2[nt][0], b2[nt][1]);
        }
    }

    const int g = lane >> 2, tq = lane & 3;
    const float* vbase = g_qkv + (size_t)(b * N_ + n0 + m0w) * QC + 2 * C_ + head * HD_;
#pragma unroll
    for (int nt = 0; nt < 8; nt++) {
        const int col = nt * 8 + tq * 2;
#pragma unroll
        for (int h = 0; h < 2; h++) {
            const int row = g + h * 8;
            float2 v = *(const float2*)(vbase + (size_t)row * QC + col);
            float Av0 = accA[nt][2*h + 0], Av1 = accA[nt][2*h + 1];
            float Bv0 = accB[nt][2*h + 0], Bv1 = accB[nt][2*h + 1];
            float sig0 = 1.f / (1.f + expf(-Bv0));
            float sig1 = 1.f / (1.f + expf(-Bv1));
            float sil0 = Bv0 * sig0, sil1 = Bv1 * sig1;
            float g0 = Av0 * sil0 - v.x;
            float g1 = Av1 * sil1 - v.y;
            float gA0 = g0 * sil0, gA1 = g1 * sil1;
            float gB0 = g0 * Av0 * sig0 * (1.f + Bv0 * (1.f - sig0));
            float gB1 = g1 * Av1 * sig1 * (1.f + Bv1 * (1.f - sig1));
            *(__half2*)&gAh[(m0w + row) * 72 + col] = __floats2half2_rn(gA0, gA1);
            *(__half2*)&gBh[(m0w + row) * 72 + col] = __floats2half2_rn(gB0, gB1);
        }
    }
    __syncthreads();

    const int mt = wid >> 1;
    const int nh = (wid & 1) * 32;
    float r1[4][4], r2[4][4];
#pragma unroll
    for (int nt = 0; nt < 4; nt++)
#pragma unroll
        for (int c = 0; c < 4; c++) { r1[nt][c] = 0.f; r2[nt][c] = 0.f; }

#pragma unroll
    for (int ks = 0; ks < 8; ks++) {
        const int k0 = ks * 16;
        const unsigned int arow = (unsigned int)(k0 + ((lane >> 4) << 3) + (lane & 7));
        const unsigned int acol = (unsigned int)(mt * 16 + (((lane >> 3) & 1) << 3));
        unsigned int a0, a1, a2, a3;
        ldm_x4t(a0, a1, a2, a3, k1u + (arow * 72 + acol) * 2);
        unsigned int bA[4][2], bB[4][2];
#pragma unroll
        for (int q = 0; q < 2; q++) {
            const unsigned int brow = (unsigned int)(k0 + (((lane >> 3) & 1) << 3) +
                                                     (lane & 7));
            const unsigned int bcol = (unsigned int)(nh + q * 16 + ((lane >> 4) << 3));
            ldm_x4t(bA[2*q][0], bA[2*q][1], bA[2*q+1][0], bA[2*q+1][1],
                    gAu + (brow * 72 + bcol) * 2);
            ldm_x4t(bB[2*q][0], bB[2*q][1], bB[2*q+1][0], bB[2*q+1][1],
                    gBu + (brow * 72 + bcol) * 2);
        }
#pragma unroll
        for (int nt = 0; nt < 4; nt++) {
            mma_f16(r1[nt][0], r1[nt][1], r1[nt][2], r1[nt][3],
                    a0, a1, a2, a3, bA[nt][0], bA[nt][1]);
            mma_f16(r2[nt][0], r2[nt][1], r2[nt][2], r2[nt][3],
                    a0, a1, a2, a3, bB[nt][0], bB[nt][1]);
        }
    }

    const int pidx = b * 8 + chunk;
    float* d1 = g_gw_part + ((size_t)(0 * NH + head) * 128 + pidx) * 4096;
    float* d2 = g_gw_part + ((size_t)(1 * NH + head) * 128 + pidx) * 4096;
#pragma unroll
    for (int nt = 0; nt < 4; nt++) {
        const int row = mt * 16 + g;
        const int col = nh + nt * 8 + tq * 2;
        float2 p;
        p.x = r1[nt][0] * M1_INV; p.y = r1[nt][1] * M1_INV;
        *(float2*)&d1[row * 64 + col] = p;
        p.x = r1[nt][2] * M1_INV; p.y = r1[nt][3] * M1_INV;
        *(float2*)&d1[(row + 8) * 64 + col] = p;
        p.x = r2[nt][0] * M1_INV; p.y = r2[nt][1] * M1_INV;
        *(float2*)&d2[row * 64 + col] = p;
        p.x = r2[nt][2] * M1_INV; p.y = r2[nt][3] * M1_INV;
        *(float2*)&d2[(row + 8) * 64 + col] = p;
    }
}

// ---------------- TTT forward kernel — HMMA, 3-term hi/lo split (unchanged) ----
#define TF_SMEM 73728
__global__ __launch_bounds__(256) void ttt_fwd_kernel()
{
    extern __shared__ __half smh[];
    const unsigned int su   = smem_to_u32(smh);
    const unsigned int w1hu = su;
    const unsigned int w1lu = su + 4608u * 2;
    const unsigned int w2hu = su + 9216u * 2;
    const unsigned int w2lu = su + 13824u * 2;
    const unsigned int q1hu = su + 18432u * 2;
    const unsigned int q1lu = su + 27648u * 2;
    __half* w1h = smh;
    __half* w1l = smh + 4608;
    __half* w2h = smh + 9216;
    __half* w2l = smh + 13824;
    __half* q1h = smh + 18432;
    __half* q1l = smh + 27648;

    const int tid = threadIdx.x, lane = tid & 31, wid = tid >> 5;
    const int chunk = blockIdx.x, head = blockIdx.y, b = blockIdx.z;
    const int n0 = chunk * 128;

    for (int idx = tid; idx < 4096; idx += 256) {
        const int k = idx >> 6, n = idx & 63;
        float v1 = g_mw1[head * 4096 + idx];
        float v2 = g_mw2[head * 4096 + idx];
        __half h1 = __float2half(v1), h2 = __float2half(v2);
        w1h[n * 72 + k] = h1;
        w1l[n * 72 + k] = __float2half(v1 - __half2float(h1));
        w2h[n * 72 + k] = h2;
        w2l[n * 72 + k] = __float2half(v2 - __half2float(h2));
    }
    {
        const float* src = g_qkv + (size_t)(b * N_ + n0) * QC + head * HD_;
        const int row = tid >> 1, c8 = (tid & 1) * 32;
#pragma unroll
        for (int c = 0; c < 32; c += 2) {
            float2 v = *(const float2*)(src + (size_t)row * QC + c8 + c);
            __half h0 = __float2half(v.x), h1 = __float2half(v.y);
            *(__half2*)&q1h[row * 72 + c8 + c] = __halves2half2(h0, h1);
            *(__half2*)&q1l[row * 72 + c8 + c] =
                __floats2half2_rn(v.x - __half2float(h0), v.y - __half2float(h1));
        }
    }
    __syncthreads();

    const int m0w = wid * 16;
    float accA[8][4], accB[8][4];
#pragma unroll
    for (int nt = 0; nt < 8; nt++)
#pragma unroll
        for (int c = 0; c < 4; c++) { accA[nt][c] = 0.f; accB[nt][c] = 0.f; }

#pragma unroll
    for (int kk = 0; kk < 4; kk++) {
        const unsigned int ak = (unsigned int)(kk * 16 + ((lane >> 4) << 3));
        const unsigned int ao = ((unsigned int)(m0w + (lane & 15)) * 72 + ak) * 2;
        unsigned int ah0, ah1, ah2, ah3, al0, al1, al2, al3;
        ldm_x4(ah0, ah1, ah2, ah3, q1hu + ao);
        ldm_x4(al0, al1, al2, al3, q1lu + ao);
        unsigned int b1h[8][2], b1l[8][2], b2h[8][2], b2l[8][2];
#pragma unroll
        for (int q = 0; q < 4; q++) {
            const unsigned int brow = (unsigned int)(q * 16 + (lane & 7) +
                                                     ((lane >> 4) << 3));
            const unsigned int bk = (unsigned int)(kk * 16 + ((lane >> 3) & 1) * 8);
            const unsigned int bo = (brow * 72 + bk) * 2;
            ldm_x4(b1h[2*q][0], b1h[2*q][1], b1h[2*q+1][0], b1h[2*q+1][1], w1hu + bo);
            ldm_x4(b1l[2*q][0], b1l[2*q][1], b1l[2*q+1][0], b1l[2*q+1][1], w1lu + bo);
            ldm_x4(b2h[2*q][0], b2h[2*q][1], b2h[2*q+1][0], b2h[2*q+1][1], w2hu + bo);
            ldm_x4(b2l[2*q][0], b2l[2*q][1], b2l[2*q+1][0], b2l[2*q+1][1], w2lu + bo);
        }
#pragma unroll
        for (int nt = 0; nt < 8; nt++) {
            mma_f16(accA[nt][0], accA[nt][1], accA[nt][2], accA[nt][3],
                    ah0, ah1, ah2, ah3, b1h[nt][0], b1h[nt][1]);
            mma_f16(accA[nt][0], accA[nt][1], accA[nt][2], accA[nt][3],
                    ah0, ah1, ah2, ah3, b1l[nt][0], b1l[nt][1]);
            mma_f16(accA[nt][0], accA[nt][1], accA[nt][2], accA[nt][3],
                    al0, al1, al2, al3, b1h[nt][0], b1h[nt][1]);
            mma_f16(accB[nt][0], accB[nt][1], accB[nt][2], accB[nt][3],
                    ah0, ah1, ah2, ah3, b2h[nt][0], b2h[nt][1]);
            mma_f16(accB[nt][0], accB[nt][1], accB[nt][2], accB[nt][3],
                    ah0, ah1, ah2, ah3, b2l[nt][0], b2l[nt][1]);
            mma_f16(accB[nt][0], accB[nt][1], accB[nt][2], accB[nt][3],
                    al0, al1, al2, al3, b2h[nt][0], b2h[nt][1]);
        }
    }

    const int g = lane >> 2, tq = lane & 3;
    __half* obase = g_xch + (size_t)(b * N_ + n0 + m0w) * XC + head * HD_;
#pragma unroll
    for (int nt = 0; nt < 8; nt++) {
        const int col = nt * 8 + tq * 2;
#pragma unroll
        for (int h = 0; h < 2; h++) {
            const int row = g + h * 8;
            float Av0 = accA[nt][2*h + 0], Av1 = accA[nt][2*h + 1];
            float Bv0 = accB[nt][2*h + 0], Bv1 = accB[nt][2*h + 1];
            float sig0 = 1.f / (1.f + expf(-Bv0));
            float sig1 = 1.f / (1.f + expf(-Bv1));
            float o0 = Av0 * (Bv0 * sig0);
            float o1 = Av1 * (Bv1 * sig1);
            *(__half2*)(obase + (size_t)row * XC + col) = __floats2half2_rn(o0, o1);
        }
    }
}

// ---------------- conv grad ----------------
__global__ __launch_bounds__(256) void conv_grad_kernel(const float* __restrict__ w3g)
{
    const int bc = blockIdx.x;
    const int b = bc >> 6, c = bc & 63;
    const int tid = threadIdx.x;
    __shared__ float k2s[32][33];
    __shared__ float wk[9];
    __shared__ float red[256];

    if (tid < 9) wk[tid] = w3g[c * 9 + tid];
    const float* base = g_qkv + (size_t)(b * N_) * QC;
    for (int p = tid; p < 1024; p += 256)
        k2s[p >> 5][p & 31] = base[(size_t)p * QC + 2368 + c];
    __syncthreads();

    float acc[9];
#pragma unroll
    for (int q = 0; q < 9; q++) acc[q] = 0.f;

    for (int p = tid; p < 1024; p += 256) {
        const int y = p >> 5, x = p & 31;
        float t[9];
#pragma unroll
        for (int dy = 0; dy < 3; dy++)
#pragma unroll
            for (int dx = 0; dx < 3; dx++) {
                int yy = y + dy - 1, xx = x + dx - 1;
                t[dy * 3 + dx] = (yy >= 0 && yy < 32 && xx >= 0 && xx < 32)
                                 ? k2s[yy][xx] : 0.f;
            }
        float f = 0.f;
#pragma unroll
        for (int q = 0; q < 9; q++) f = fmaf(wk[q], t[q], f);
        float v = base[(size_t)p * QC + 2432 + c];
        float g = (f - v) * M2_INV;
#pragma unroll
        for (int q = 0; q < 9; q++) acc[q] = fmaf(g, t[q], acc[q]);
    }

    for (int q = 0; q < 9; q++) {
        red[tid] = acc[q];
        __syncthreads();
        for (int s = 128; s > 0; s >>= 1) {
            if (tid < s) red[tid] += red[tid + s];
            __syncthreads();
        }
        if (tid == 0) g_gw3_part[(size_t)bc * 9 + q] = red[0];
        __syncthreads();
    }
}

__global__ void conv_grad_reduce_kernel()
{
    const int tid = threadIdx.x;
    __shared__ float red[576];
    float s = 0.f;
    const int c = tid / 9, q = tid % 9;
    for (int b = 0; b < B_; b++) s += g_gw3_part[(size_t)(b * 64 + c) * 9 + q];
    g_gw3[tid] = s;
    red[tid] = s * s;
    __syncthreads();
    if (tid < 64) red[tid] += red[tid + 512];
    __syncthreads();
    for (int st = 256; st > 0; st >>= 1) {
        if (tid < st && tid + st < 576) red[tid] += red[tid + st];
        __syncthreads();
    }
    if (tid == 0) g_sumsq[24] = red[0];
}

// ---------------- two-stage gw reduce ----------------
__global__ __launch_bounds__(256) void reduce_gw_stage1()
{
    const int th = blockIdx.x >> 3;
    const int g  = blockIdx.x & 7;
    const int tid = threadIdx.x;
    const float* src = g_gw_part + ((size_t)th * 128 + g * 16) * 4096;
    float s[16];
#pragma unroll
    for (int q = 0; q < 16; q++) s[q] = 0.f;
    for (int p = 0; p < 16; p++) {
        const float* row = src + (size_t)p * 4096 + tid;
#pragma unroll
        for (int q = 0; q < 16; q++) s[q] += row[q * 256];
    }
    float* dst = g_gw_stage + (size_t)(th * 8 + g) * 4096 + tid;
#pragma unroll
    for (int q = 0; q < 16; q++) dst[q * 256] = s[q];
}

__global__ __launch_bounds__(256) void reduce_gw_stage2()
{
    const int th  = blockIdx.x;
    const int tid = threadIdx.x;
    const float* src = g_gw_stage + (size_t)th * 8 * 4096;
    float* dst = g_gw + (size_t)th * 4096;

    float s[16];
#pragma unroll
    for (int q = 0; q < 16; q++) s[q] = 0.f;
    for (int p = 0; p < 8; p++) {
        const float* row = src + (size_t)p * 4096 + tid;
#pragma unroll
        for (int q = 0; q < 16; q++) s[q] += row[q * 256];
    }
    float ss = 0.f;
#pragma unroll
    for (int q = 0; q < 16; q++) { dst[tid + q * 256] = s[q]; ss += s[q] * s[q]; }

    __shared__ float red[256];
    red[tid] = ss;
    __syncthreads();
    for (int st = 128; st > 0; st >>= 1) {
        if (tid < st) red[tid] += red[tid + st];
        __syncthreads();
    }
    if (tid == 0) g_sumsq[th] = red[0];
}

// ---------------- weight update (scales fused) ----------------
__global__ void update_w_kernel(const float* __restrict__ w1g,
                                const float* __restrict__ w2g,
                                const float* __restrict__ w3g)
{
    __shared__ float sc[3];
    if (threadIdx.x == 0) {
        float s1 = 0.f, s2 = 0.f;
        for (int h = 0; h < NH; h++) { s1 += g_sumsq[h]; s2 += g_sumsq[NH + h]; }
        sc[0] = LR_ / (sqrtf(s1) + 1.f);
        sc[1] = LR_ / (sqrtf(s2) + 1.f);
        sc[2] = LR_ / (sqrtf(g_sumsq[24]) + 1.f);
    }
    __syncthreads();
    const int i = blockIdx.x * 256 + threadIdx.x;
    if (i < 49152) {
        g_mw1[i] = w1g[i] - sc[0] * g_gw[i];
    } else if (i < 98304) {
        const int k = i - 49152;
        g_mw2[k] = w2g[k] - sc[1] * g_gw[49152 + k];
    } else if (i < 98880) {
        const int k = i - 98304;
        g_mw3[k] = w3g[k] - sc[2] * g_gw3[k];
    }
}

// ---------------- conv forward (writes fp16 hi directly) ----------------
__global__ __launch_bounds__(256) void conv_fwd_kernel()
{
    const int bc = blockIdx.x;
    const int b = bc >> 6, c = bc & 63;
    const int tid = threadIdx.x;
    __shared__ float q2s[32][33];
    __shared__ float wk[9];
    if (tid < 9) wk[tid] = g_mw3[c * 9 + tid];
    const float* base = g_qkv + (size_t)(b * N_) * QC;
    for (int p = tid; p < 1024; p += 256)
        q2s[p >> 5][p & 31] = base[(size_t)p * QC + 2304 + c];
    __syncthreads();

    for (int p = tid; p < 1024; p += 256) {
        const int y = p >> 5, x = p & 31;
        float f = 0.f;
#pragma unroll
        for (int dy = 0; dy < 3; dy++)
#pragma unroll
            for (int dx = 0; dx < 3; dx++) {
                int yy = y + dy - 1, xx = x + dx - 1;
                if (yy >= 0 && yy < 32 && xx >= 0 && xx < 32)
                    f = fmaf(wk[dy * 3 + dx], q2s[yy][xx], f);
            }
        g_xch[(size_t)(b * N_ + p) * XC + 768 + c] = __float2half(f);
    }
}

// ---------------- launch ----------------
extern "C" void kernel_launch(void* const* d_in, const int* in_sizes, int n_in,
                              void* d_out, int out_size)
{
    const float *x = nullptr, *Wqkv = nullptr, *bqkv = nullptr, *w1 = nullptr,
                *w2 = nullptr, *w3 = nullptr, *Wproj = nullptr, *bproj = nullptr;
    for (int i = 0; i < n_in; i++) {
        const int s = in_sizes[i];
        const float* p = (const float*)d_in[i];
        if      (s == B_*N_*C_)   x = p;
        else if (s == C_*QC)      Wqkv = p;
        else if (s == QC)         bqkv = p;
        else if (s == NH*HD_*HD_) { if (!w1) w1 = p; else w2 = p; }
        else if (s == 64*9)       w3 = p;
        else if (s == XC*C_)      Wproj = p;
        else if (s == C_)         bproj = p;
    }

    float* qkv_ptr = nullptr;
    __half *xh, *xch, *wqh, *wph;
    cudaGetSymbolAddress((void**)&qkv_ptr, g_qkv);
    cudaGetSymbolAddress((void**)&xh,  g_xh);
    cudaGetSymbolAddress((void**)&xch, g_xch);
    cudaGetSymbolAddress((void**)&wqh, g_wqh);
    cudaGetSymbolAddress((void**)&wph, g_wph);

    cudaFuncSetAttribute(ttt_grad_kernel,
        cudaFuncAttributeMaxDynamicSharedMemorySize, TG_SMEM);
    cudaFuncSetAttribute(ttt_fwd_kernel,
        cudaFuncAttributeMaxDynamicSharedMemorySize, TF_SMEM);
    cudaFuncSetAttribute(tc_gemm,
        cudaFuncAttributeMaxDynamicSharedMemorySize, TCG_SMEM);

    // 1. convert x, transpose weights (plain fp16)
    convert_f16<<<(B_*N_*C_/4 + 255)/256, 256>>>(x, xh, B_*N_*C_/4);
    transpose_f16<<<dim3(QC/32, C_/32), 256>>>(Wqkv, wqh, C_, QC);
    transpose_f16<<<dim3(C_/32, XC/32), 256>>>(Wproj, wph, XC, C_);

    // 2. qkv = x @ Wqkv + bqkv  (fp16 HMMA, 64x64 warp tiles, BK=64)
    tc_gemm<<<dim3((QC + 127)/128, (B_*N_)/128), 128, TCG_SMEM>>>(
        xh, wqh, bqkv, qkv_ptr, QC, C_);

    // 3. TTT (HMMA) + conv gradients, reduce, update
    ttt_grad_kernel<<<dim3(8, NH, B_), 256, TG_SMEM>>>(w1, w2);
    conv_grad_kernel<<<B_ * 64, 256>>>(w3);
    conv_grad_reduce_kernel<<<1, 576>>>();
    reduce_gw_stage1<<<192, 256>>>();
    reduce_gw_stage2<<<24, 256>>>();
    update_w_kernel<<<(98880 + 255)/256, 256>>>(w1, w2, w3);

    // 4. post-update forward (HMMA, 3-term split)
    ttt_fwd_kernel<<<dim3(8, NH, B_), 256, TF_SMEM>>>();
    conv_fwd_kernel<<<B_ * 64, 256>>>();

    // 5. proj GEMM (fp16 HMMA, 64x64 warp tiles, BK=64)
    tc_gemm<<<dim3(C_/128, (B_*N_)/128), 128, TCG_SMEM>>>(
        xch, wph, bproj, (float*)d_out, C_, XC);
}

// round 16
// speedup vs baseline: 1.4183x; 1.4183x over previous
#include <cuda_runtime.h>
#include <cuda_bf16.h>
#include <cuda_fp16.h>
#include <cstdint>
#include <cstdio>
#include <math.h>

#define B_  16
#define N_  1024
#define C_  768
#define NH  12
#define HD_ 64
#define QC  2496   // 3*768 + 3*64
#define XC  832    // 768 + 64
#define M1_INV (1.0f/12582912.0f)
#define M2_INV (1.0f/1048576.0f)
#define LR_ 0.001f

// ---------------- scratch ----------------
__device__ float g_qkv[B_*N_*QC];
__device__ float g_gw_part[2*NH*128*HD_*HD_];
__device__ float g_gw_stage[24*8*HD_*HD_];
__device__ float g_gw[2*NH*HD_*HD_];
__device__ float g_gw3_part[B_*64*9];
__device__ float g_gw3[64*9];
__device__ float g_sumsq[25];
__device__ float g_mw1[NH*HD_*HD_];
__device__ float g_mw2[NH*HD_*HD_];
__device__ float g_mw3[64*9];
// fp16 operands (plain fp16, no splits)
__device__ __half g_xh[B_*N_*C_];
__device__ __half g_xch[B_*N_*XC];
__device__ __half g_wqh[QC*C_];   // [N=2496][K=768]
__device__ __half g_wph[C_*XC];   // [N=768][K=832]

// ---------------- PTX helpers ----------------
__device__ __forceinline__ unsigned int smem_to_u32(const void* smem_ptr) {
    unsigned int addr;
    asm("{ .reg .u64 tmp; cvta.to.shared.u64 tmp, %1; cvt.u32.u64 %0, tmp; }"
        : "=r"(addr) : "l"(smem_ptr));
    return addr;
}
__device__ __forceinline__ void cp_async16(unsigned int saddr, const void* gaddr) {
    asm volatile("cp.async.cg.shared.global [%0], [%1], 16;"
                 :: "r"(saddr), "l"(gaddr) : "memory");
}
__device__ __forceinline__ void cp_commit() {
    asm volatile("cp.async.commit_group;" ::: "memory");
}
__device__ __forceinline__ void cp_wait1() {
    asm volatile("cp.async.wait_group 1;" ::: "memory");
}
__device__ __forceinline__ void cp_wait0() {
    asm volatile("cp.async.wait_group 0;" ::: "memory");
}
__device__ __forceinline__ void ldm_x4(unsigned int& r0, unsigned int& r1,
                                       unsigned int& r2, unsigned int& r3,
                                       unsigned int a) {
    asm volatile("ldmatrix.sync.aligned.m8n8.x4.shared.b16 {%0,%1,%2,%3}, [%4];"
                 : "=r"(r0), "=r"(r1), "=r"(r2), "=r"(r3) : "r"(a));
}
__device__ __forceinline__ void ldm_x4t(unsigned int& r0, unsigned int& r1,
                                        unsigned int& r2, unsigned int& r3,
                                        unsigned int a) {
    asm volatile("ldmatrix.sync.aligned.m8n8.x4.trans.shared.b16 {%0,%1,%2,%3}, [%4];"
                 : "=r"(r0), "=r"(r1), "=r"(r2), "=r"(r3) : "r"(a));
}
__device__ __forceinline__ void mma_f16(float& c0, float& c1, float& c2, float& c3,
                                        unsigned int a0, unsigned int a1,
                                        unsigned int a2, unsigned int a3,
                                        unsigned int b0, unsigned int b1) {
    asm volatile("mma.sync.aligned.m16n8k16.row.col.f32.f16.f16.f32 "
                 "{%0,%1,%2,%3}, {%4,%5,%6,%7}, {%8,%9}, {%0,%1,%2,%3};"
                 : "+f"(c0), "+f"(c1), "+f"(c2), "+f"(c3)
                 : "r"(a0), "r"(a1), "r"(a2), "r"(a3), "r"(b0), "r"(b1));
}

// ---------------- conversions ----------------
__device__ __forceinline__ unsigned int pack_h2(__half a, __half b) {
    return (unsigned int)__half_as_ushort(a) |
           ((unsigned int)__half_as_ushort(b) << 16);
}
__global__ __launch_bounds__(256) void convert_f16(
    const float* __restrict__ X, __half* __restrict__ H, int n4)
{
    int i = blockIdx.x * 256 + threadIdx.x;
    if (i >= n4) return;
    float4 v = ((const float4*)X)[i];
    uint2 hh;
    hh.x = pack_h2(__float2half(v.x), __float2half(v.y));
    hh.y = pack_h2(__float2half(v.z), __float2half(v.w));
    ((uint2*)H)[i] = hh;
}
// W[K][N] -> T[N][K] fp16 (no split)
__global__ __launch_bounds__(256) void transpose_f16(
    const float* __restrict__ W, __half* __restrict__ Th, int K, int N)
{
    __shared__ float s[32][33];
    const int n0 = blockIdx.x * 32, k0 = blockIdx.y * 32;
    const int tx = threadIdx.x & 31, ty = threadIdx.x >> 5;
    for (int r = ty; r < 32; r += 8)
        s[r][tx] = W[(size_t)(k0 + r) * N + n0 + tx];
    __syncthreads();
    for (int r = ty; r < 32; r += 8)
        Th[(size_t)(n0 + r) * K + k0 + tx] = __float2half(s[tx][r]);
}

// ---------------- HMMA GEMM (fp16, 4 warps x 64x64 tiles, BK=64, coalesced) ---
#define SROW   72
#define ARR_B  (128*SROW*2)       // 18432 bytes per array
#define STG_B  (2*ARR_B)          // 36864 bytes per stage
#define TCG_SMEM (2*STG_B)        // 73728

__global__ __launch_bounds__(128) void tc_gemm(
    const __half* __restrict__ Ah, const __half* __restrict__ Bh,
    const float* __restrict__ bias, float* __restrict__ C,
    int Nfull, int K)
{
    extern __shared__ __half smb[];
    const unsigned int smem_u = smem_to_u32(smb);
    const int t = threadIdx.x, lane = t & 31, wid = t >> 5;    // 4 warps
    const int m0 = blockIdx.y * 128, n0 = blockIdx.x * 128;
    const int wm = (wid >> 1) * 64, wn = (wid & 1) * 64;

    float acc[4][8][4];
#pragma unroll
    for (int a = 0; a < 4; a++)
#pragma unroll
        for (int b = 0; b < 8; b++)
#pragma unroll
            for (int c = 0; c < 4; c++) acc[a][b][c] = 0.f;

    // load plan (coalesced): chunk c = j*128 + t -> row = j*16 + (t>>3),
    // chunk-in-row = t&7. 8 consecutive threads read 128B contiguous global.
    const int rbase = t >> 3, c8 = (t & 7) * 8;
    const unsigned int s0 = (unsigned int)((rbase * SROW + c8) * 2);
    const unsigned int sstep = (unsigned int)(16 * SROW * 2);
    bool vB[8];
    size_t offA[8], offB[8];
#pragma unroll
    for (int j = 0; j < 8; j++) {
        const int rr = rbase + 16 * j;
        vB[j]   = (n0 + rr) < Nfull;
        offA[j] = (size_t)(m0 + rr) * K + c8;
        offB[j] = (size_t)(vB[j] ? (n0 + rr) : 0) * K + c8;
    }

#define ISSUE(stg, ks) do {                                                  \
        unsigned int _sb = smem_u + (unsigned int)(stg) * STG_B;             \
        const int _ko = (ks) * 64;                                           \
        _Pragma("unroll")                                                    \
        for (int j = 0; j < 8; j++) {                                        \
            unsigned int _s = _sb + s0 + (unsigned int)j * sstep;            \
            cp_async16(_s,          Ah + offA[j] + _ko);                     \
            if (vB[j]) cp_async16(_s + ARR_B, Bh + offB[j] + _ko);           \
        }                                                                    \
        cp_commit();                                                         \
    } while (0)

    const int nk = K / 64;
    ISSUE(0, 0);

    for (int s = 0; s < nk; s++) {
        if (s + 1 < nk) { ISSUE((s + 1) & 1, s + 1); cp_wait1(); }
        else            { cp_wait0(); }
        __syncthreads();

        const unsigned int sb = smem_u + (unsigned int)(s & 1) * STG_B;
#pragma unroll
        for (int kc = 0; kc < 64; kc += 16) {
            // B fragments: 8 n-tiles via 4 ldm_x4
            unsigned int bh[8][2];
#pragma unroll
            for (int q = 0; q < 4; q++) {
                unsigned int brow = (unsigned int)(wn + q * 16 + (lane & 7) +
                                                   ((lane >> 4) << 3));
                unsigned int koff = (unsigned int)(((lane >> 3) & 1) * 8);
                unsigned int ab = sb + 1u * ARR_B + (brow * SROW + kc + koff) * 2;
                ldm_x4(bh[2*q][0], bh[2*q][1], bh[2*q+1][0], bh[2*q+1][1], ab);
            }
#pragma unroll
            for (int mt = 0; mt < 4; mt++) {
                unsigned int arow = (unsigned int)(wm + mt * 16 + (lane & 15));
                unsigned int koff = (unsigned int)((lane >> 4) * 8);
                unsigned int aa = sb + (arow * SROW + kc + koff) * 2;
                unsigned int a0, a1, a2, a3;
                ldm_x4(a0, a1, a2, a3, aa);
#pragma unroll
                for (int nt = 0; nt < 8; nt++)
                    mma_f16(acc[mt][nt][0], acc[mt][nt][1],
                            acc[mt][nt][2], acc[mt][nt][3],
                            a0, a1, a2, a3, bh[nt][0], bh[nt][1]);
            }
        }
        __syncthreads();
    }
#undef ISSUE

    const int g = lane >> 2, tq = lane & 3;
#pragma unroll
    for (int mt = 0; mt < 4; mt++) {
        const int row = m0 + wm + mt * 16 + g;
#pragma unroll
        for (int nt = 0; nt < 8; nt++) {
            const int col = n0 + wn + nt * 8 + tq * 2;
            if (col < Nfull) {
                float b0 = bias[col], b1 = bias[col + 1];
                float2 o1; o1.x = acc[mt][nt][0] + b0; o1.y = acc[mt][nt][1] + b1;
                float2 o2v; o2v.x = acc[mt][nt][2] + b0; o2v.y = acc[mt][nt][3] + b1;
                *(float2*)(C + (size_t)row * Nfull + col) = o1;
                *(float2*)(C + (size_t)(row + 8) * Nfull + col) = o2v;
            }
        }
    }
}

// ---------------- TTT gradient kernel — HMMA (unchanged) ----------------
#define TG_SMEM 73728
__global__ __launch_bounds__(256) void ttt_grad_kernel(
    const float* __restrict__ w1g, const float* __restrict__ w2g)
{
    extern __shared__ __half smh[];
    const unsigned int su  = smem_to_u32(smh);
    const unsigned int w1u = su;
    const unsigned int w2u = su + 4608u * 2;
    const unsigned int k1u = su + 9216u * 2;
    const unsigned int gAu = k1u + 9216u * 2;
    const unsigned int gBu = gAu + 9216u * 2;
    __half* w1T = smh;
    __half* w2T = smh + 4608;
    __half* k1h = smh + 9216;
    __half* gAh = smh + 9216 + 9216;
    __half* gBh = gAh + 9216;

    const int tid = threadIdx.x, lane = tid & 31, wid = tid >> 5;
    const int chunk = blockIdx.x, head = blockIdx.y, b = blockIdx.z;
    const int n0 = chunk * 128;

    for (int idx = tid; idx < 4096; idx += 256) {
        const int k = idx >> 6, n = idx & 63;
        w1T[n * 72 + k] = __float2half(w1g[head * 4096 + idx]);
        w2T[n * 72 + k] = __float2half(w2g[head * 4096 + idx]);
    }
    {
        const float* src = g_qkv + (size_t)(b * N_ + n0) * QC + C_ + head * HD_;
        const int row = tid >> 1, c8 = (tid & 1) * 32;
#pragma unroll
        for (int c = 0; c < 32; c += 4) {
            float4 v = *(const float4*)(src + (size_t)row * QC + c8 + c);
            *(__half2*)&k1h[row * 72 + c8 + c]     = __floats2half2_rn(v.x, v.y);
            *(__half2*)&k1h[row * 72 + c8 + c + 2] = __floats2half2_rn(v.z, v.w);
        }
    }
    __syncthreads();

    const int m0w = wid * 16;
    float accA[8][4], accB[8][4];
#pragma unroll
    for (int nt = 0; nt < 8; nt++)
#pragma unroll
        for (int c = 0; c < 4; c++) { accA[nt][c] = 0.f; accB[nt][c] = 0.f; }

#pragma unroll
    for (int kk = 0; kk < 4; kk++) {
        const unsigned int ak = (unsigned int)(kk * 16 + ((lane >> 4) << 3));
        const unsigned int aa = k1u + ((unsigned int)(m0w + (lane & 15)) * 72 + ak) * 2;
        unsigned int a0, a1, a2, a3;
        ldm_x4(a0, a1, a2, a3, aa);
        unsigned int b1[8][2], b2[8][2];
#pragma unroll
        for (int q = 0; q < 4; q++) {
            const unsigned int brow = (unsigned int)(q * 16 + (lane & 7) +
                                                     ((lane >> 4) << 3));
            const unsigned int bk = (unsigned int)(kk * 16 + ((lane >> 3) & 1) * 8);
            ldm_x4(b1[2*q][0], b1[2*q][1], b1[2*q+1][0], b1[2*q+1][1],
                   w1u + (brow * 72 + bk) * 2);
            ldm_x4(b2[2*q][0], b2[2*q][1], b2[2*q+1][0], b2[2*q+1][1],
                   w2u + (brow * 72 + bk) * 2);
        }
#pragma unroll
        for (int nt = 0; nt < 8; nt++) {
            mma_f16(accA[nt][0], accA[nt][1], accA[nt][2], accA[nt][3],
                    a0, a1, a2, a3, b1[nt][0], b1[nt][1]);
            mma_f16(accB[nt][0], accB[nt][1], accB[nt][2], accB[nt][3],
                    a0, a1, a2, a3, b2[nt][0], b2[nt][1]);
        }
    }

    const int g = lane >> 2, tq = lane & 3;
    const float* vbase = g_qkv + (size_t)(b * N_ + n0 + m0w) * QC + 2 * C_ + head * HD_;
#pragma unroll
    for (int nt = 0; nt < 8; nt++) {
        const int col = nt * 8 + tq * 2;
#pragma unroll
        for (int h = 0; h < 2; h++) {
            const int row = g + h * 8;
            float2 v = *(const float2*)(vbase + (size_t)row * QC + col);
            float Av0 = accA[nt][2*h + 0], Av1 = accA[nt][2*h + 1];
            float Bv0 = accB[nt][2*h + 0], Bv1 = accB[nt][2*h + 1];
            float sig0 = 1.f / (1.f + expf(-Bv0));
            float sig1 = 1.f / (1.f + expf(-Bv1));
            float sil0 = Bv0 * sig0, sil1 = Bv1 * sig1;
            float g0 = Av0 * sil0 - v.x;
            float g1 = Av1 * sil1 - v.y;
            float gA0 = g0 * sil0, gA1 = g1 * sil1;
            float gB0 = g0 * Av0 * sig0 * (1.f + Bv0 * (1.f - sig0));
            float gB1 = g1 * Av1 * sig1 * (1.f + Bv1 * (1.f - sig1));
            *(__half2*)&gAh[(m0w + row) * 72 + col] = __floats2half2_rn(gA0, gA1);
            *(__half2*)&gBh[(m0w + row) * 72 + col] = __floats2half2_rn(gB0, gB1);
        }
    }
    __syncthreads();

    const int mt = wid >> 1;
    const int nh = (wid & 1) * 32;
    float r1[4][4], r2[4][4];
#pragma unroll
    for (int nt = 0; nt < 4; nt++)
#pragma unroll
        for (int c = 0; c < 4; c++) { r1[nt][c] = 0.f; r2[nt][c] = 0.f; }

#pragma unroll
    for (int ks = 0; ks < 8; ks++) {
        const int k0 = ks * 16;
        const unsigned int arow = (unsigned int)(k0 + ((lane >> 4) << 3) + (lane & 7));
        const unsigned int acol = (unsigned int)(mt * 16 + (((lane >> 3) & 1) << 3));
        unsigned int a0, a1, a2, a3;
        ldm_x4t(a0, a1, a2, a3, k1u + (arow * 72 + acol) * 2);
        unsigned int bA[4][2], bB[4][2];
#pragma unroll
        for (int q = 0; q < 2; q++) {
            const unsigned int brow = (unsigned int)(k0 + (((lane >> 3) & 1) << 3) +
                                                     (lane & 7));
            const unsigned int bcol = (unsigned int)(nh + q * 16 + ((lane >> 4) << 3));
            ldm_x4t(bA[2*q][0], bA[2*q][1], bA[2*q+1][0], bA[2*q+1][1],
                    gAu + (brow * 72 + bcol) * 2);
            ldm_x4t(bB[2*q][0], bB[2*q][1], bB[2*q+1][0], bB[2*q+1][1],
                    gBu + (brow * 72 + bcol) * 2);
        }
#pragma unroll
        for (int nt = 0; nt < 4; nt++) {
            mma_f16(r1[nt][0], r1[nt][1], r1[nt][2], r1[nt][3],
                    a0, a1, a2, a3, bA[nt][0], bA[nt][1]);
            mma_f16(r2[nt][0], r2[nt][1], r2[nt][2], r2[nt][3],
                    a0, a1, a2, a3, bB[nt][0], bB[nt][1]);
        }
    }

    const int pidx = b * 8 + chunk;
    float* d1 = g_gw_part + ((size_t)(0 * NH + head) * 128 + pidx) * 4096;
    float* d2 = g_gw_part + ((size_t)(1 * NH + head) * 128 + pidx) * 4096;
#pragma unroll
    for (int nt = 0; nt < 4; nt++) {
        const int row = mt * 16 + g;
        const int col = nh + nt * 8 + tq * 2;
        float2 p;
        p.x = r1[nt][0] * M1_INV; p.y = r1[nt][1] * M1_INV;
        *(float2*)&d1[row * 64 + col] = p;
        p.x = r1[nt][2] * M1_INV; p.y = r1[nt][3] * M1_INV;
        *(float2*)&d1[(row + 8) * 64 + col] = p;
        p.x = r2[nt][0] * M1_INV; p.y = r2[nt][1] * M1_INV;
        *(float2*)&d2[row * 64 + col] = p;
        p.x = r2[nt][2] * M1_INV; p.y = r2[nt][3] * M1_INV;
        *(float2*)&d2[(row + 8) * 64 + col] = p;
    }
}

// ---------------- TTT forward kernel — HMMA, 3-term hi/lo split (unchanged) ----
#define TF_SMEM 73728
__global__ __launch_bounds__(256) void ttt_fwd_kernel()
{
    extern __shared__ __half smh[];
    const unsigned int su   = smem_to_u32(smh);
    const unsigned int w1hu = su;
    const unsigned int w1lu = su + 4608u * 2;
    const unsigned int w2hu = su + 9216u * 2;
    const unsigned int w2lu = su + 13824u * 2;
    const unsigned int q1hu = su + 18432u * 2;
    const unsigned int q1lu = su + 27648u * 2;
    __half* w1h = smh;
    __half* w1l = smh + 4608;
    __half* w2h = smh + 9216;
    __half* w2l = smh + 13824;
    __half* q1h = smh + 18432;
    __half* q1l = smh + 27648;

    const int tid = threadIdx.x, lane = tid & 31, wid = tid >> 5;
    const int chunk = blockIdx.x, head = blockIdx.y, b = blockIdx.z;
    const int n0 = chunk * 128;

    for (int idx = tid; idx < 4096; idx += 256) {
        const int k = idx >> 6, n = idx & 63;
        float v1 = g_mw1[head * 4096 + idx];
        float v2 = g_mw2[head * 4096 + idx];
        __half h1 = __float2half(v1), h2 = __float2half(v2);
        w1h[n * 72 + k] = h1;
        w1l[n * 72 + k] = __float2half(v1 - __half2float(h1));
        w2h[n * 72 + k] = h2;
        w2l[n * 72 + k] = __float2half(v2 - __half2float(h2));
    }
    {
        const float* src = g_qkv + (size_t)(b * N_ + n0) * QC + head * HD_;
        const int row = tid >> 1, c8 = (tid & 1) * 32;
#pragma unroll
        for (int c = 0; c < 32; c += 2) {
            float2 v = *(const float2*)(src + (size_t)row * QC + c8 + c);
            __half h0 = __float2half(v.x), h1 = __float2half(v.y);
            *(__half2*)&q1h[row * 72 + c8 + c] = __halves2half2(h0, h1);
            *(__half2*)&q1l[row * 72 + c8 + c] =
                __floats2half2_rn(v.x - __half2float(h0), v.y - __half2float(h1));
        }
    }
    __syncthreads();

    const int m0w = wid * 16;
    float accA[8][4], accB[8][4];
#pragma unroll
    for (int nt = 0; nt < 8; nt++)
#pragma unroll
        for (int c = 0; c < 4; c++) { accA[nt][c] = 0.f; accB[nt][c] = 0.f; }

#pragma unroll
    for (int kk = 0; kk < 4; kk++) {
        const unsigned int ak = (unsigned int)(kk * 16 + ((lane >> 4) << 3));
        const unsigned int ao = ((unsigned int)(m0w + (lane & 15)) * 72 + ak) * 2;
        unsigned int ah0, ah1, ah2, ah3, al0, al1, al2, al3;
        ldm_x4(ah0, ah1, ah2, ah3, q1hu + ao);
        ldm_x4(al0, al1, al2, al3, q1lu + ao);
        unsigned int b1h[8][2], b1l[8][2], b2h[8][2], b2l[8][2];
#pragma unroll
        for (int q = 0; q < 4; q++) {
            const unsigned int brow = (unsigned int)(q * 16 + (lane & 7) +
                                                     ((lane >> 4) << 3));
            const unsigned int bk = (unsigned int)(kk * 16 + ((lane >> 3) & 1) * 8);
            const unsigned int bo = (brow * 72 + bk) * 2;
            ldm_x4(b1h[2*q][0], b1h[2*q][1], b1h[2*q+1][0], b1h[2*q+1][1], w1hu + bo);
            ldm_x4(b1l[2*q][0], b1l[2*q][1], b1l[2*q+1][0], b1l[2*q+1][1], w1lu + bo);
            ldm_x4(b2h[2*q][0], b2h[2*q][1], b2h[2*q+1][0], b2h[2*q+1][1], w2hu + bo);
            ldm_x4(b2l[2*q][0], b2l[2*q][1], b2l[2*q+1][0], b2l[2*q+1][1], w2lu + bo);
        }
#pragma unroll
        for (int nt = 0; nt < 8; nt++) {
            mma_f16(accA[nt][0], accA[nt][1], accA[nt][2], accA[nt][3],
                    ah0, ah1, ah2, ah3, b1h[nt][0], b1h[nt][1]);
            mma_f16(accA[nt][0], accA[nt][1], accA[nt][2], accA[nt][3],
                    ah0, ah1, ah2, ah3, b1l[nt][0], b1l[nt][1]);
            mma_f16(accA[nt][0], accA[nt][1], accA[nt][2], accA[nt][3],
                    al0, al1, al2, al3, b1h[nt][0], b1h[nt][1]);
            mma_f16(accB[nt][0], accB[nt][1], accB[nt][2], accB[nt][3],
                    ah0, ah1, ah2, ah3, b2h[nt][0], b2h[nt][1]);
            mma_f16(accB[nt][0], accB[nt][1], accB[nt][2], accB[nt][3],
                    ah0, ah1, ah2, ah3, b2l[nt][0], b2l[nt][1]);
            mma_f16(accB[nt][0], accB[nt][1], accB[nt][2], accB[nt][3],
                    al0, al1, al2, al3, b2h[nt][0], b2h[nt][1]);
        }
    }

    const int g = lane >> 2, tq = lane & 3;
    __half* obase = g_xch + (size_t)(b * N_ + n0 + m0w) * XC + head * HD_;
#pragma unroll
    for (int nt = 0; nt < 8; nt++) {
        const int col = nt * 8 + tq * 2;
#pragma unroll
        for (int h = 0; h < 2; h++) {
            const int row = g + h * 8;
            float Av0 = accA[nt][2*h + 0], Av1 = accA[nt][2*h + 1];
            float Bv0 = accB[nt][2*h + 0], Bv1 = accB[nt][2*h + 1];
            float sig0 = 1.f / (1.f + expf(-Bv0));
            float sig1 = 1.f / (1.f + expf(-Bv1));
            float o0 = Av0 * (Bv0 * sig0);
            float o1 = Av1 * (Bv1 * sig1);
            *(__half2*)(obase + (size_t)row * XC + col) = __floats2half2_rn(o0, o1);
        }
    }
}

// ---------------- conv grad ----------------
__global__ __launch_bounds__(256) void conv_grad_kernel(const float* __restrict__ w3g)
{
    const int bc = blockIdx.x;
    const int b = bc >> 6, c = bc & 63;
    const int tid = threadIdx.x;
    __shared__ float k2s[32][33];
    __shared__ float wk[9];
    __shared__ float red[256];

    if (tid < 9) wk[tid] = w3g[c * 9 + tid];
    const float* base = g_qkv + (size_t)(b * N_) * QC;
    for (int p = tid; p < 1024; p += 256)
        k2s[p >> 5][p & 31] = base[(size_t)p * QC + 2368 + c];
    __syncthreads();

    float acc[9];
#pragma unroll
    for (int q = 0; q < 9; q++) acc[q] = 0.f;

    for (int p = tid; p < 1024; p += 256) {
        const int y = p >> 5, x = p & 31;
        float t[9];
#pragma unroll
        for (int dy = 0; dy < 3; dy++)
#pragma unroll
            for (int dx = 0; dx < 3; dx++) {
                int yy = y + dy - 1, xx = x + dx - 1;
                t[dy * 3 + dx] = (yy >= 0 && yy < 32 && xx >= 0 && xx < 32)
                                 ? k2s[yy][xx] : 0.f;
            }
        float f = 0.f;
#pragma unroll
        for (int q = 0; q < 9; q++) f = fmaf(wk[q], t[q], f);
        float v = base[(size_t)p * QC + 2432 + c];
        float g = (f - v) * M2_INV;
#pragma unroll
        for (int q = 0; q < 9; q++) acc[q] = fmaf(g, t[q], acc[q]);
    }

    for (int q = 0; q < 9; q++) {
        red[tid] = acc[q];
        __syncthreads();
        for (int s = 128; s > 0; s >>= 1) {
            if (tid < s) red[tid] += red[tid + s];
            __syncthreads();
        }
        if (tid == 0) g_gw3_part[(size_t)bc * 9 + q] = red[0];
        __syncthreads();
    }
}

__global__ void conv_grad_reduce_kernel()
{
    const int tid = threadIdx.x;
    __shared__ float red[576];
    float s = 0.f;
    const int c = tid / 9, q = tid % 9;
    for (int b = 0; b < B_; b++) s += g_gw3_part[(size_t)(b * 64 + c) * 9 + q];
    g_gw3[tid] = s;
    red[tid] = s * s;
    __syncthreads();
    if (tid < 64) red[tid] += red[tid + 512];
    __syncthreads();
    for (int st = 256; st > 0; st >>= 1) {
        if (tid < st && tid + st < 576) red[tid] += red[tid + st];
        __syncthreads();
    }
    if (tid == 0) g_sumsq[24] = red[0];
}

// ---------------- two-stage gw reduce ----------------
__global__ __launch_bounds__(256) void reduce_gw_stage1()
{
    const int th = blockIdx.x >> 3;
    const int g  = blockIdx.x & 7;
    const int tid = threadIdx.x;
    const float* src = g_gw_part + ((size_t)th * 128 + g * 16) * 4096;
    float s[16];
#pragma unroll
    for (int q = 0; q < 16; q++) s[q] = 0.f;
    for (int p = 0; p < 16; p++) {
        const float* row = src + (size_t)p * 4096 + tid;
#pragma unroll
        for (int q = 0; q < 16; q++) s[q] += row[q * 256];
    }
    float* dst = g_gw_stage + (size_t)(th * 8 + g) * 4096 + tid;
#pragma unroll
    for (int q = 0; q < 16; q++) dst[q * 256] = s[q];
}

__global__ __launch_bounds__(256) void reduce_gw_stage2()
{
    const int th  = blockIdx.x;
    const int tid = threadIdx.x;
    const float* src = g_gw_stage + (size_t)th * 8 * 4096;
    float* dst = g_gw + (size_t)th * 4096;

    float s[16];
#pragma unroll
    for (int q = 0; q < 16; q++) s[q] = 0.f;
    for (int p = 0; p < 8; p++) {
        const float* row = src + (size_t)p * 4096 + tid;
#pragma unroll
        for (int q = 0; q < 16; q++) s[q] += row[q * 256];
    }
    float ss = 0.f;
#pragma unroll
    for (int q = 0; q < 16; q++) { dst[tid + q * 256] = s[q]; ss += s[q] * s[q]; }

    __shared__ float red[256];
    red[tid] = ss;
    __syncthreads();
    for (int st = 128; st > 0; st >>= 1) {
        if (tid < st) red[tid] += red[tid + st];
        __syncthreads();
    }
    if (tid == 0) g_sumsq[th] = red[0];
}

// ---------------- weight update (scales fused) ----------------
__global__ void update_w_kernel(const float* __restrict__ w1g,
                                const float* __restrict__ w2g,
                                const float* __restrict__ w3g)
{
    __shared__ float sc[3];
    if (threadIdx.x == 0) {
        float s1 = 0.f, s2 = 0.f;
        for (int h = 0; h < NH; h++) { s1 += g_sumsq[h]; s2 += g_sumsq[NH + h]; }
        sc[0] = LR_ / (sqrtf(s1) + 1.f);
        sc[1] = LR_ / (sqrtf(s2) + 1.f);
        sc[2] = LR_ / (sqrtf(g_sumsq[24]) + 1.f);
    }
    __syncthreads();
    const int i = blockIdx.x * 256 + threadIdx.x;
    if (i < 49152) {
        g_mw1[i] = w1g[i] - sc[0] * g_gw[i];
    } else if (i < 98304) {
        const int k = i - 49152;
        g_mw2[k] = w2g[k] - sc[1] * g_gw[49152 + k];
    } else if (i < 98880) {
        const int k = i - 98304;
        g_mw3[k] = w3g[k] - sc[2] * g_gw3[k];
    }
}

// ---------------- conv forward (writes fp16 hi directly) ----------------
__global__ __launch_bounds__(256) void conv_fwd_kernel()
{
    const int bc = blockIdx.x;
    const int b = bc >> 6, c = bc & 63;
    const int tid = threadIdx.x;
    __shared__ float q2s[32][33];
    __shared__ float wk[9];
    if (tid < 9) wk[tid] = g_mw3[c * 9 + tid];
    const float* base = g_qkv + (size_t)(b * N_) * QC;
    for (int p = tid; p < 1024; p += 256)
        q2s[p >> 5][p & 31] = base[(size_t)p * QC + 2304 + c];
    __syncthreads();

    for (int p = tid; p < 1024; p += 256) {
        const int y = p >> 5, x = p & 31;
        float f = 0.f;
#pragma unroll
        for (int dy = 0; dy < 3; dy++)
#pragma unroll
            for (int dx = 0; dx < 3; dx++) {
                int yy = y + dy - 1, xx = x + dx - 1;
                if (yy >= 0 && yy < 32 && xx >= 0 && xx < 32)
                    f = fmaf(wk[dy * 3 + dx], q2s[yy][xx], f);
            }
        g_xch[(size_t)(b * N_ + p) * XC + 768 + c] = __float2half(f);
    }
}

// ---------------- launch ----------------
extern "C" void kernel_launch(void* const* d_in, const int* in_sizes, int n_in,
                              void* d_out, int out_size)
{
    const float *x = nullptr, *Wqkv = nullptr, *bqkv = nullptr, *w1 = nullptr,
                *w2 = nullptr, *w3 = nullptr, *Wproj = nullptr, *bproj = nullptr;
    for (int i = 0; i < n_in; i++) {
        const int s = in_sizes[i];
        const float* p = (const float*)d_in[i];
        if      (s == B_*N_*C_)   x = p;
        else if (s == C_*QC)      Wqkv = p;
        else if (s == QC)         bqkv = p;
        else if (s == NH*HD_*HD_) { if (!w1) w1 = p; else w2 = p; }
        else if (s == 64*9)       w3 = p;
        else if (s == XC*C_)      Wproj = p;
        else if (s == C_)         bproj = p;
    }

    float* qkv_ptr = nullptr;
    __half *xh, *xch, *wqh, *wph;
    cudaGetSymbolAddress((void**)&qkv_ptr, g_qkv);
    cudaGetSymbolAddress((void**)&xh,  g_xh);
    cudaGetSymbolAddress((void**)&xch, g_xch);
    cudaGetSymbolAddress((void**)&wqh, g_wqh);
    cudaGetSymbolAddress((void**)&wph, g_wph);

    cudaFuncSetAttribute(ttt_grad_kernel,
        cudaFuncAttributeMaxDynamicSharedMemorySize, TG_SMEM);
    cudaFuncSetAttribute(ttt_fwd_kernel,
        cudaFuncAttributeMaxDynamicSharedMemorySize, TF_SMEM);
    cudaFuncSetAttribute(tc_gemm,
        cudaFuncAttributeMaxDynamicSharedMemorySize, TCG_SMEM);

    // 1. convert x, transpose weights (plain fp16)
    convert_f16<<<(B_*N_*C_/4 + 255)/256, 256>>>(x, xh, B_*N_*C_/4);
    transpose_f16<<<dim3(QC/32, C_/32), 256>>>(Wqkv, wqh, C_, QC);
    transpose_f16<<<dim3(C_/32, XC/32), 256>>>(Wproj, wph, XC, C_);

    // 2. qkv = x @ Wqkv + bqkv  (fp16 HMMA, 64x64 warp tiles, BK=64 coalesced)
    tc_gemm<<<dim3((QC + 127)/128, (B_*N_)/128), 128, TCG_SMEM>>>(
        xh, wqh, bqkv, qkv_ptr, QC, C_);

    // 3. TTT (HMMA) + conv gradients, reduce, update
    ttt_grad_kernel<<<dim3(8, NH, B_), 256, TG_SMEM>>>(w1, w2);
    conv_grad_kernel<<<B_ * 64, 256>>>(w3);
    conv_grad_reduce_kernel<<<1, 576>>>();
    reduce_gw_stage1<<<192, 256>>>();
    reduce_gw_stage2<<<24, 256>>>();
    update_w_kernel<<<(98880 + 255)/256, 256>>>(w1, w2, w3);

    // 4. post-update forward (HMMA, 3-term split)
    ttt_fwd_kernel<<<dim3(8, NH, B_), 256, TF_SMEM>>>();
    conv_fwd_kernel<<<B_ * 64, 256>>>();

    // 5. proj GEMM (fp16 HMMA, 64x64 warp tiles, BK=64 coalesced)
    tc_gemm<<<dim3(C_/128, (B_*N_)/128), 128, TCG_SMEM>>>(
        xch, wph, bproj, (float*)d_out, C_, XC);
}

// round 17
// speedup vs baseline: 1.5204x; 1.0720x over previous
#include <cuda_runtime.h>
#include <cuda_bf16.h>
#include <cuda_fp16.h>
#include <cstdint>
#include <cstdio>
#include <math.h>

#define B_  16
#define N_  1024
#define C_  768
#define NH  12
#define HD_ 64
#define QC  2496   // 3*768 + 3*64
#define XC  832    // 768 + 64
#define M1_INV (1.0f/12582912.0f)
#define M2_INV (1.0f/1048576.0f)
#define LR_ 0.001f

// ---------------- scratch ----------------
__device__ __half g_qkvh[B_*N_*QC];               // fp16 qkv intermediate (82 MB)
__device__ float g_gw_part[2*NH*128*HD_*HD_];
__device__ float g_gw_stage[24*8*HD_*HD_];
__device__ float g_gw[2*NH*HD_*HD_];
__device__ float g_gw3_part[B_*64*9];
__device__ float g_gw3[64*9];
__device__ float g_sumsq[25];
__device__ float g_mw1[NH*HD_*HD_];
__device__ float g_mw2[NH*HD_*HD_];
__device__ float g_mw3[64*9];
__device__ __half g_xh[B_*N_*C_];
__device__ __half g_xch[B_*N_*XC];
__device__ __half g_wqh[QC*C_];   // [N=2496][K=768]
__device__ __half g_wph[C_*XC];   // [N=768][K=832]

// ---------------- PTX helpers ----------------
__device__ __forceinline__ unsigned int smem_to_u32(const void* smem_ptr) {
    unsigned int addr;
    asm("{ .reg .u64 tmp; cvta.to.shared.u64 tmp, %1; cvt.u32.u64 %0, tmp; }"
        : "=r"(addr) : "l"(smem_ptr));
    return addr;
}
__device__ __forceinline__ void cp_async16(unsigned int saddr, const void* gaddr) {
    asm volatile("cp.async.cg.shared.global [%0], [%1], 16;"
                 :: "r"(saddr), "l"(gaddr) : "memory");
}
__device__ __forceinline__ void cp_commit() {
    asm volatile("cp.async.commit_group;" ::: "memory");
}
__device__ __forceinline__ void cp_wait1() {
    asm volatile("cp.async.wait_group 1;" ::: "memory");
}
__device__ __forceinline__ void cp_wait0() {
    asm volatile("cp.async.wait_group 0;" ::: "memory");
}
__device__ __forceinline__ void ldm_x4(unsigned int& r0, unsigned int& r1,
                                       unsigned int& r2, unsigned int& r3,
                                       unsigned int a) {
    asm volatile("ldmatrix.sync.aligned.m8n8.x4.shared.b16 {%0,%1,%2,%3}, [%4];"
                 : "=r"(r0), "=r"(r1), "=r"(r2), "=r"(r3) : "r"(a));
}
__device__ __forceinline__ void ldm_x4t(unsigned int& r0, unsigned int& r1,
                                        unsigned int& r2, unsigned int& r3,
                                        unsigned int a) {
    asm volatile("ldmatrix.sync.aligned.m8n8.x4.trans.shared.b16 {%0,%1,%2,%3}, [%4];"
                 : "=r"(r0), "=r"(r1), "=r"(r2), "=r"(r3) : "r"(a));
}
__device__ __forceinline__ void mma_f16(float& c0, float& c1, float& c2, float& c3,
                                        unsigned int a0, unsigned int a1,
                                        unsigned int a2, unsigned int a3,
                                        unsigned int b0, unsigned int b1) {
    asm volatile("mma.sync.aligned.m16n8k16.row.col.f32.f16.f16.f32 "
                 "{%0,%1,%2,%3}, {%4,%5,%6,%7}, {%8,%9}, {%0,%1,%2,%3};"
                 : "+f"(c0), "+f"(c1), "+f"(c2), "+f"(c3)
                 : "r"(a0), "r"(a1), "r"(a2), "r"(a3), "r"(b0), "r"(b1));
}

// ---------------- conversions ----------------
__device__ __forceinline__ unsigned int pack_h2(__half a, __half b) {
    return (unsigned int)__half_as_ushort(a) |
           ((unsigned int)__half_as_ushort(b) << 16);
}
__global__ __launch_bounds__(256) void convert_f16(
    const float* __restrict__ X, __half* __restrict__ H, int n4)
{
    int i = blockIdx.x * 256 + threadIdx.x;
    if (i >= n4) return;
    float4 v = ((const float4*)X)[i];
    uint2 hh;
    hh.x = pack_h2(__float2half(v.x), __float2half(v.y));
    hh.y = pack_h2(__float2half(v.z), __float2half(v.w));
    ((uint2*)H)[i] = hh;
}
// W[K][N] -> T[N][K] fp16
__global__ __launch_bounds__(256) void transpose_f16(
    const float* __restrict__ W, __half* __restrict__ Th, int K, int N)
{
    __shared__ float s[32][33];
    const int n0 = blockIdx.x * 32, k0 = blockIdx.y * 32;
    const int tx = threadIdx.x & 31, ty = threadIdx.x >> 5;
    for (int r = ty; r < 32; r += 8)
        s[r][tx] = W[(size_t)(k0 + r) * N + n0 + tx];
    __syncthreads();
    for (int r = ty; r < 32; r += 8)
        Th[(size_t)(n0 + r) * K + k0 + tx] = __float2half(s[tx][r]);
}

// ---------------- HMMA GEMM (fp16, 4 warps x 64x64, BK=64, coalesced) ---------
// out_half: 1 -> write __half output, 0 -> fp32.
#define SROW   72
#define ARR_B  (128*SROW*2)       // 18432 bytes per array
#define STG_B  (2*ARR_B)          // 36864 bytes per stage
#define TCG_SMEM (2*STG_B)        // 73728

__global__ __launch_bounds__(128) void tc_gemm(
    const __half* __restrict__ Ah, const __half* __restrict__ Bh,
    const float* __restrict__ bias, void* __restrict__ Cout,
    int out_half, int Nfull, int K)
{
    extern __shared__ __half smb[];
    const unsigned int smem_u = smem_to_u32(smb);
    const int t = threadIdx.x, lane = t & 31, wid = t >> 5;
    const int m0 = blockIdx.y * 128, n0 = blockIdx.x * 128;
    const int wm = (wid >> 1) * 64, wn = (wid & 1) * 64;

    float acc[4][8][4];
#pragma unroll
    for (int a = 0; a < 4; a++)
#pragma unroll
        for (int b = 0; b < 8; b++)
#pragma unroll
            for (int c = 0; c < 4; c++) acc[a][b][c] = 0.f;

    const int rbase = t >> 3, c8 = (t & 7) * 8;
    const unsigned int s0 = (unsigned int)((rbase * SROW + c8) * 2);
    const unsigned int sstep = (unsigned int)(16 * SROW * 2);
    bool vB[8];
    size_t offA[8], offB[8];
#pragma unroll
    for (int j = 0; j < 8; j++) {
        const int rr = rbase + 16 * j;
        vB[j]   = (n0 + rr) < Nfull;
        offA[j] = (size_t)(m0 + rr) * K + c8;
        offB[j] = (size_t)(vB[j] ? (n0 + rr) : 0) * K + c8;
    }

#define ISSUE(stg, ks) do {                                                  \
        unsigned int _sb = smem_u + (unsigned int)(stg) * STG_B;             \
        const int _ko = (ks) * 64;                                           \
        _Pragma("unroll")                                                    \
        for (int j = 0; j < 8; j++) {                                        \
            unsigned int _s = _sb + s0 + (unsigned int)j * sstep;            \
            cp_async16(_s,          Ah + offA[j] + _ko);                     \
            if (vB[j]) cp_async16(_s + ARR_B, Bh + offB[j] + _ko);           \
        }                                                                    \
        cp_commit();                                                         \
    } while (0)

    const int nk = K / 64;
    ISSUE(0, 0);

    for (int s = 0; s < nk; s++) {
        if (s + 1 < nk) { ISSUE((s + 1) & 1, s + 1); cp_wait1(); }
        else            { cp_wait0(); }
        __syncthreads();

        const unsigned int sb = smem_u + (unsigned int)(s & 1) * STG_B;
#pragma unroll
        for (int kc = 0; kc < 64; kc += 16) {
            unsigned int bh[8][2];
#pragma unroll
            for (int q = 0; q < 4; q++) {
                unsigned int brow = (unsigned int)(wn + q * 16 + (lane & 7) +
                                                   ((lane >> 4) << 3));
                unsigned int koff = (unsigned int)(((lane >> 3) & 1) * 8);
                unsigned int ab = sb + 1u * ARR_B + (brow * SROW + kc + koff) * 2;
                ldm_x4(bh[2*q][0], bh[2*q][1], bh[2*q+1][0], bh[2*q+1][1], ab);
            }
#pragma unroll
            for (int mt = 0; mt < 4; mt++) {
                unsigned int arow = (unsigned int)(wm + mt * 16 + (lane & 15));
                unsigned int koff = (unsigned int)((lane >> 4) * 8);
                unsigned int aa = sb + (arow * SROW + kc + koff) * 2;
                unsigned int a0, a1, a2, a3;
                ldm_x4(a0, a1, a2, a3, aa);
#pragma unroll
                for (int nt = 0; nt < 8; nt++)
                    mma_f16(acc[mt][nt][0], acc[mt][nt][1],
                            acc[mt][nt][2], acc[mt][nt][3],
                            a0, a1, a2, a3, bh[nt][0], bh[nt][1]);
            }
        }
        __syncthreads();
    }
#undef ISSUE

    const int g = lane >> 2, tq = lane & 3;
    if (out_half) {
        __half* Ch = (__half*)Cout;
#pragma unroll
        for (int mt = 0; mt < 4; mt++) {
            const int row = m0 + wm + mt * 16 + g;
#pragma unroll
            for (int nt = 0; nt < 8; nt++) {
                const int col = n0 + wn + nt * 8 + tq * 2;
                if (col < Nfull) {
                    float b0 = bias[col], b1 = bias[col + 1];
                    *(__half2*)(Ch + (size_t)row * Nfull + col) =
                        __floats2half2_rn(acc[mt][nt][0] + b0, acc[mt][nt][1] + b1);
                    *(__half2*)(Ch + (size_t)(row + 8) * Nfull + col) =
                        __floats2half2_rn(acc[mt][nt][2] + b0, acc[mt][nt][3] + b1);
                }
            }
        }
    } else {
        float* Cf = (float*)Cout;
#pragma unroll
        for (int mt = 0; mt < 4; mt++) {
            const int row = m0 + wm + mt * 16 + g;
#pragma unroll
            for (int nt = 0; nt < 8; nt++) {
                const int col = n0 + wn + nt * 8 + tq * 2;
                if (col < Nfull) {
                    float b0 = bias[col], b1 = bias[col + 1];
                    float2 o1; o1.x = acc[mt][nt][0] + b0; o1.y = acc[mt][nt][1] + b1;
                    float2 o2v; o2v.x = acc[mt][nt][2] + b0; o2v.y = acc[mt][nt][3] + b1;
                    *(float2*)(Cf + (size_t)row * Nfull + col) = o1;
                    *(float2*)(Cf + (size_t)(row + 8) * Nfull + col) = o2v;
                }
            }
        }
    }
}

// ---------------- TTT gradient kernel — HMMA, fp16 qkv inputs ----------------
#define TG_SMEM 73728
__global__ __launch_bounds__(256) void ttt_grad_kernel(
    const float* __restrict__ w1g, const float* __restrict__ w2g)
{
    extern __shared__ __half smh[];
    const unsigned int su  = smem_to_u32(smh);
    const unsigned int w1u = su;
    const unsigned int w2u = su + 4608u * 2;
    const unsigned int k1u = su + 9216u * 2;
    const unsigned int gAu = k1u + 9216u * 2;
    const unsigned int gBu = gAu + 9216u * 2;
    __half* w1T = smh;
    __half* w2T = smh + 4608;
    __half* k1h = smh + 9216;
    __half* gAh = smh + 9216 + 9216;
    __half* gBh = gAh + 9216;

    const int tid = threadIdx.x, lane = tid & 31, wid = tid >> 5;
    const int chunk = blockIdx.x, head = blockIdx.y, b = blockIdx.z;
    const int n0 = chunk * 128;

    for (int idx = tid; idx < 4096; idx += 256) {
        const int k = idx >> 6, n = idx & 63;
        w1T[n * 72 + k] = __float2half(w1g[head * 4096 + idx]);
        w2T[n * 72 + k] = __float2half(w2g[head * 4096 + idx]);
    }
    {   // k1: fp16 copy (no conversion)
        const __half* src = g_qkvh + (size_t)(b * N_ + n0) * QC + C_ + head * HD_;
        const int row = tid >> 1, c8 = (tid & 1) * 32;
#pragma unroll
        for (int c = 0; c < 32; c += 8) {
            uint4 v = *(const uint4*)(src + (size_t)row * QC + c8 + c);
            *(uint4*)&k1h[row * 72 + c8 + c] = v;
        }
    }
    __syncthreads();

    const int m0w = wid * 16;
    float accA[8][4], accB[8][4];
#pragma unroll
    for (int nt = 0; nt < 8; nt++)
#pragma unroll
        for (int c = 0; c < 4; c++) { accA[nt][c] = 0.f; accB[nt][c] = 0.f; }

#pragma unroll
    for (int kk = 0; kk < 4; kk++) {
        const unsigned int ak = (unsigned int)(kk * 16 + ((lane >> 4) << 3));
        const unsigned int aa = k1u + ((unsigned int)(m0w + (lane & 15)) * 72 + ak) * 2;
        unsigned int a0, a1, a2, a3;
        ldm_x4(a0, a1, a2, a3, aa);
        unsigned int b1[8][2], b2[8][2];
#pragma unroll
        for (int q = 0; q < 4; q++) {
            const unsigned int brow = (unsigned int)(q * 16 + (lane & 7) +
                                                     ((lane >> 4) << 3));
            const unsigned int bk = (unsigned int)(kk * 16 + ((lane >> 3) & 1) * 8);
            ldm_x4(b1[2*q][0], b1[2*q][1], b1[2*q+1][0], b1[2*q+1][1],
                   w1u + (brow * 72 + bk) * 2);
            ldm_x4(b2[2*q][0], b2[2*q][1], b2[2*q+1][0], b2[2*q+1][1],
                   w2u + (brow * 72 + bk) * 2);
        }
#pragma unroll
        for (int nt = 0; nt < 8; nt++) {
            mma_f16(accA[nt][0], accA[nt][1], accA[nt][2], accA[nt][3],
                    a0, a1, a2, a3, b1[nt][0], b1[nt][1]);
            mma_f16(accB[nt][0], accB[nt][1], accB[nt][2], accB[nt][3],
                    a0, a1, a2, a3, b2[nt][0], b2[nt][1]);
        }
    }

    const int g = lane >> 2, tq = lane & 3;
    const __half* vbase = g_qkvh + (size_t)(b * N_ + n0 + m0w) * QC + 2 * C_ + head * HD_;
#pragma unroll
    for (int nt = 0; nt < 8; nt++) {
        const int col = nt * 8 + tq * 2;
#pragma unroll
        for (int h = 0; h < 2; h++) {
            const int row = g + h * 8;
            float2 v = __half22float2(*(const __half2*)(vbase + (size_t)row * QC + col));
            float Av0 = accA[nt][2*h + 0], Av1 = accA[nt][2*h + 1];
            float Bv0 = accB[nt][2*h + 0], Bv1 = accB[nt][2*h + 1];
            float sig0 = 1.f / (1.f + expf(-Bv0));
            float sig1 = 1.f / (1.f + expf(-Bv1));
            float sil0 = Bv0 * sig0, sil1 = Bv1 * sig1;
            float g0 = Av0 * sil0 - v.x;
            float g1 = Av1 * sil1 - v.y;
            float gA0 = g0 * sil0, gA1 = g1 * sil1;
            float gB0 = g0 * Av0 * sig0 * (1.f + Bv0 * (1.f - sig0));
            float gB1 = g1 * Av1 * sig1 * (1.f + Bv1 * (1.f - sig1));
            *(__half2*)&gAh[(m0w + row) * 72 + col] = __floats2half2_rn(gA0, gA1);
            *(__half2*)&gBh[(m0w + row) * 72 + col] = __floats2half2_rn(gB0, gB1);
        }
    }
    __syncthreads();

    const int mt = wid >> 1;
    const int nh = (wid & 1) * 32;
    float r1[4][4], r2[4][4];
#pragma unroll
    for (int nt = 0; nt < 4; nt++)
#pragma unroll
        for (int c = 0; c < 4; c++) { r1[nt][c] = 0.f; r2[nt][c] = 0.f; }

#pragma unroll
    for (int ks = 0; ks < 8; ks++) {
        const int k0 = ks * 16;
        const unsigned int arow = (unsigned int)(k0 + ((lane >> 4) << 3) + (lane & 7));
        const unsigned int acol = (unsigned int)(mt * 16 + (((lane >> 3) & 1) << 3));
        unsigned int a0, a1, a2, a3;
        ldm_x4t(a0, a1, a2, a3, k1u + (arow * 72 + acol) * 2);
        unsigned int bA[4][2], bB[4][2];
#pragma unroll
        for (int q = 0; q < 2; q++) {
            const unsigned int brow = (unsigned int)(k0 + (((lane >> 3) & 1) << 3) +
                                                     (lane & 7));
            const unsigned int bcol = (unsigned int)(nh + q * 16 + ((lane >> 4) << 3));
            ldm_x4t(bA[2*q][0], bA[2*q][1], bA[2*q+1][0], bA[2*q+1][1],
                    gAu + (brow * 72 + bcol) * 2);
            ldm_x4t(bB[2*q][0], bB[2*q][1], bB[2*q+1][0], bB[2*q+1][1],
                    gBu + (brow * 72 + bcol) * 2);
        }
#pragma unroll
        for (int nt = 0; nt < 4; nt++) {
            mma_f16(r1[nt][0], r1[nt][1], r1[nt][2], r1[nt][3],
                    a0, a1, a2, a3, bA[nt][0], bA[nt][1]);
            mma_f16(r2[nt][0], r2[nt][1], r2[nt][2], r2[nt][3],
                    a0, a1, a2, a3, bB[nt][0], bB[nt][1]);
        }
    }

    const int pidx = b * 8 + chunk;
    float* d1 = g_gw_part + ((size_t)(0 * NH + head) * 128 + pidx) * 4096;
    float* d2 = g_gw_part + ((size_t)(1 * NH + head) * 128 + pidx) * 4096;
#pragma unroll
    for (int nt = 0; nt < 4; nt++) {
        const int row = mt * 16 + g;
        const int col = nh + nt * 8 + tq * 2;
        float2 p;
        p.x = r1[nt][0] * M1_INV; p.y = r1[nt][1] * M1_INV;
        *(float2*)&d1[row * 64 + col] = p;
        p.x = r1[nt][2] * M1_INV; p.y = r1[nt][3] * M1_INV;
        *(float2*)&d1[(row + 8) * 64 + col] = p;
        p.x = r2[nt][0] * M1_INV; p.y = r2[nt][1] * M1_INV;
        *(float2*)&d2[row * 64 + col] = p;
        p.x = r2[nt][2] * M1_INV; p.y = r2[nt][3] * M1_INV;
        *(float2*)&d2[(row + 8) * 64 + col] = p;
    }
}

// ---------------- TTT forward kernel — HMMA, fp16 q1 + weight hi/lo split ------
// SMEM: w1h/w1l/w2h/w2l [64][72] + q1h [128][72] = 27648 halves = 55296 B
#define TF_SMEM 55296
__global__ __launch_bounds__(256) void ttt_fwd_kernel()
{
    extern __shared__ __half smh[];
    const unsigned int su   = smem_to_u32(smh);
    const unsigned int w1hu = su;
    const unsigned int w1lu = su + 4608u * 2;
    const unsigned int w2hu = su + 9216u * 2;
    const unsigned int w2lu = su + 13824u * 2;
    const unsigned int q1hu = su + 18432u * 2;
    __half* w1h = smh;
    __half* w1l = smh + 4608;
    __half* w2h = smh + 9216;
    __half* w2l = smh + 13824;
    __half* q1h = smh + 18432;

    const int tid = threadIdx.x, lane = tid & 31, wid = tid >> 5;
    const int chunk = blockIdx.x, head = blockIdx.y, b = blockIdx.z;
    const int n0 = chunk * 128;

    for (int idx = tid; idx < 4096; idx += 256) {
        const int k = idx >> 6, n = idx & 63;
        float v1 = g_mw1[head * 4096 + idx];
        float v2 = g_mw2[head * 4096 + idx];
        __half h1 = __float2half(v1), h2 = __float2half(v2);
        w1h[n * 72 + k] = h1;
        w1l[n * 72 + k] = __float2half(v1 - __half2float(h1));
        w2h[n * 72 + k] = h2;
        w2l[n * 72 + k] = __float2half(v2 - __half2float(h2));
    }
    {   // q1: fp16 copy
        const __half* src = g_qkvh + (size_t)(b * N_ + n0) * QC + head * HD_;
        const int row = tid >> 1, c8 = (tid & 1) * 32;
#pragma unroll
        for (int c = 0; c < 32; c += 8) {
            uint4 v = *(const uint4*)(src + (size_t)row * QC + c8 + c);
            *(uint4*)&q1h[row * 72 + c8 + c] = v;
        }
    }
    __syncthreads();

    const int m0w = wid * 16;
    float accA[8][4], accB[8][4];
#pragma unroll
    for (int nt = 0; nt < 8; nt++)
#pragma unroll
        for (int c = 0; c < 4; c++) { accA[nt][c] = 0.f; accB[nt][c] = 0.f; }

#pragma unroll
    for (int kk = 0; kk < 4; kk++) {
        const unsigned int ak = (unsigned int)(kk * 16 + ((lane >> 4) << 3));
        const unsigned int ao = ((unsigned int)(m0w + (lane & 15)) * 72 + ak) * 2;
        unsigned int ah0, ah1, ah2, ah3;
        ldm_x4(ah0, ah1, ah2, ah3, q1hu + ao);
        unsigned int b1h[8][2], b1l[8][2], b2h[8][2], b2l[8][2];
#pragma unroll
        for (int q = 0; q < 4; q++) {
            const unsigned int brow = (unsigned int)(q * 16 + (lane & 7) +
                                                     ((lane >> 4) << 3));
            const unsigned int bk = (unsigned int)(kk * 16 + ((lane >> 3) & 1) * 8);
            const unsigned int bo = (brow * 72 + bk) * 2;
            ldm_x4(b1h[2*q][0], b1h[2*q][1], b1h[2*q+1][0], b1h[2*q+1][1], w1hu + bo);
            ldm_x4(b1l[2*q][0], b1l[2*q][1], b1l[2*q+1][0], b1l[2*q+1][1], w1lu + bo);
            ldm_x4(b2h[2*q][0], b2h[2*q][1], b2h[2*q+1][0], b2h[2*q+1][1], w2hu + bo);
            ldm_x4(b2l[2*q][0], b2l[2*q][1], b2l[2*q+1][0], b2l[2*q+1][1], w2lu + bo);
        }
#pragma unroll
        for (int nt = 0; nt < 8; nt++) {
            mma_f16(accA[nt][0], accA[nt][1], accA[nt][2], accA[nt][3],
                    ah0, ah1, ah2, ah3, b1h[nt][0], b1h[nt][1]);
            mma_f16(accA[nt][0], accA[nt][1], accA[nt][2], accA[nt][3],
                    ah0, ah1, ah2, ah3, b1l[nt][0], b1l[nt][1]);
            mma_f16(accB[nt][0], accB[nt][1], accB[nt][2], accB[nt][3],
                    ah0, ah1, ah2, ah3, b2h[nt][0], b2h[nt][1]);
            mma_f16(accB[nt][0], accB[nt][1], accB[nt][2], accB[nt][3],
                    ah0, ah1, ah2, ah3, b2l[nt][0], b2l[nt][1]);
        }
    }

    const int g = lane >> 2, tq = lane & 3;
    __half* obase = g_xch + (size_t)(b * N_ + n0 + m0w) * XC + head * HD_;
#pragma unroll
    for (int nt = 0; nt < 8; nt++) {
        const int col = nt * 8 + tq * 2;
#pragma unroll
        for (int h = 0; h < 2; h++) {
            const int row = g + h * 8;
            float Av0 = accA[nt][2*h + 0], Av1 = accA[nt][2*h + 1];
            float Bv0 = accB[nt][2*h + 0], Bv1 = accB[nt][2*h + 1];
            float sig0 = 1.f / (1.f + expf(-Bv0));
            float sig1 = 1.f / (1.f + expf(-Bv1));
            float o0 = Av0 * (Bv0 * sig0);
            float o1 = Av1 * (Bv1 * sig1);
            *(__half2*)(obase + (size_t)row * XC + col) = __floats2half2_rn(o0, o1);
        }
    }
}

// ---------------- conv grad (fp16 qkv inputs) ----------------
__global__ __launch_bounds__(256) void conv_grad_kernel(const float* __restrict__ w3g)
{
    const int bc = blockIdx.x;
    const int b = bc >> 6, c = bc & 63;
    const int tid = threadIdx.x;
    __shared__ float k2s[32][33];
    __shared__ float wk[9];
    __shared__ float red[256];

    if (tid < 9) wk[tid] = w3g[c * 9 + tid];
    const __half* base = g_qkvh + (size_t)(b * N_) * QC;
    for (int p = tid; p < 1024; p += 256)
        k2s[p >> 5][p & 31] = __half2float(base[(size_t)p * QC + 2368 + c]);
    __syncthreads();

    float acc[9];
#pragma unroll
    for (int q = 0; q < 9; q++) acc[q] = 0.f;

    for (int p = tid; p < 1024; p += 256) {
        const int y = p >> 5, x = p & 31;
        float t[9];
#pragma unroll
        for (int dy = 0; dy < 3; dy++)
#pragma unroll
            for (int dx = 0; dx < 3; dx++) {
                int yy = y + dy - 1, xx = x + dx - 1;
                t[dy * 3 + dx] = (yy >= 0 && yy < 32 && xx >= 0 && xx < 32)
                                 ? k2s[yy][xx] : 0.f;
            }
        float f = 0.f;
#pragma unroll
        for (int q = 0; q < 9; q++) f = fmaf(wk[q], t[q], f);
        float v = __half2float(base[(size_t)p * QC + 2432 + c]);
        float g = (f - v) * M2_INV;
#pragma unroll
        for (int q = 0; q < 9; q++) acc[q] = fmaf(g, t[q], acc[q]);
    }

    for (int q = 0; q < 9; q++) {
        red[tid] = acc[q];
        __syncthreads();
        for (int s = 128; s > 0; s >>= 1) {
            if (tid < s) red[tid] += red[tid + s];
            __syncthreads();
        }
        if (tid == 0) g_gw3_part[(size_t)bc * 9 + q] = red[0];
        __syncthreads();
    }
}

__global__ void conv_grad_reduce_kernel()
{
    const int tid = threadIdx.x;
    __shared__ float red[576];
    float s = 0.f;
    const int c = tid / 9, q = tid % 9;
    for (int b = 0; b < B_; b++) s += g_gw3_part[(size_t)(b * 64 + c) * 9 + q];
    g_gw3[tid] = s;
    red[tid] = s * s;
    __syncthreads();
    if (tid < 64) red[tid] += red[tid + 512];
    __syncthreads();
    for (int st = 256; st > 0; st >>= 1) {
        if (tid < st && tid + st < 576) red[tid] += red[tid + st];
        __syncthreads();
    }
    if (tid == 0) g_sumsq[24] = red[0];
}

// ---------------- two-stage gw reduce ----------------
__global__ __launch_bounds__(256) void reduce_gw_stage1()
{
    const int th = blockIdx.x >> 3;
    const int g  = blockIdx.x & 7;
    const int tid = threadIdx.x;
    const float* src = g_gw_part + ((size_t)th * 128 + g * 16) * 4096;
    float s[16];
#pragma unroll
    for (int q = 0; q < 16; q++) s[q] = 0.f;
    for (int p = 0; p < 16; p++) {
        const float* row = src + (size_t)p * 4096 + tid;
#pragma unroll
        for (int q = 0; q < 16; q++) s[q] += row[q * 256];
    }
    float* dst = g_gw_stage + (size_t)(th * 8 + g) * 4096 + tid;
#pragma unroll
    for (int q = 0; q < 16; q++) dst[q * 256] = s[q];
}

__global__ __launch_bounds__(256) void reduce_gw_stage2()
{
    const int th  = blockIdx.x;
    const int tid = threadIdx.x;
    const float* src = g_gw_stage + (size_t)th * 8 * 4096;
    float* dst = g_gw + (size_t)th * 4096;

    float s[16];
#pragma unroll
    for (int q = 0; q < 16; q++) s[q] = 0.f;
    for (int p = 0; p < 8; p++) {
        const float* row = src + (size_t)p * 4096 + tid;
#pragma unroll
        for (int q = 0; q < 16; q++) s[q] += row[q * 256];
    }
    float ss = 0.f;
#pragma unroll
    for (int q = 0; q < 16; q++) { dst[tid + q * 256] = s[q]; ss += s[q] * s[q]; }

    __shared__ float red[256];
    red[tid] = ss;
    __syncthreads();
    for (int st = 128; st > 0; st >>= 1) {
        if (tid < st) red[tid] += red[tid + st];
        __syncthreads();
    }
    if (tid == 0) g_sumsq[th] = red[0];
}

// ---------------- weight update (scales fused) ----------------
__global__ void update_w_kernel(const float* __restrict__ w1g,
                                const float* __restrict__ w2g,
                                const float* __restrict__ w3g)
{
    __shared__ float sc[3];
    if (threadIdx.x == 0) {
        float s1 = 0.f, s2 = 0.f;
        for (int h = 0; h < NH; h++) { s1 += g_sumsq[h]; s2 += g_sumsq[NH + h]; }
        sc[0] = LR_ / (sqrtf(s1) + 1.f);
        sc[1] = LR_ / (sqrtf(s2) + 1.f);
        sc[2] = LR_ / (sqrtf(g_sumsq[24]) + 1.f);
    }
    __syncthreads();
    const int i = blockIdx.x * 256 + threadIdx.x;
    if (i < 49152) {
        g_mw1[i] = w1g[i] - sc[0] * g_gw[i];
    } else if (i < 98304) {
        const int k = i - 49152;
        g_mw2[k] = w2g[k] - sc[1] * g_gw[49152 + k];
    } else if (i < 98880) {
        const int k = i - 98304;
        g_mw3[k] = w3g[k] - sc[2] * g_gw3[k];
    }
}

// ---------------- conv forward (fp16 in, fp16 out) ----------------
__global__ __launch_bounds__(256) void conv_fwd_kernel()
{
    const int bc = blockIdx.x;
    const int b = bc >> 6, c = bc & 63;
    const int tid = threadIdx.x;
    __shared__ float q2s[32][33];
    __shared__ float wk[9];
    if (tid < 9) wk[tid] = g_mw3[c * 9 + tid];
    const __half* base = g_qkvh + (size_t)(b * N_) * QC;
    for (int p = tid; p < 1024; p += 256)
        q2s[p >> 5][p & 31] = __half2float(base[(size_t)p * QC + 2304 + c]);
    __syncthreads();

    for (int p = tid; p < 1024; p += 256) {
        const int y = p >> 5, x = p & 31;
        float f = 0.f;
#pragma unroll
        for (int dy = 0; dy < 3; dy++)
#pragma unroll
            for (int dx = 0; dx < 3; dx++) {
                int yy = y + dy - 1, xx = x + dx - 1;
                if (yy >= 0 && yy < 32 && xx >= 0 && xx < 32)
                    f = fmaf(wk[dy * 3 + dx], q2s[yy][xx], f);
            }
        g_xch[(size_t)(b * N_ + p) * XC + 768 + c] = __float2half(f);
    }
}

// ---------------- launch ----------------
extern "C" void kernel_launch(void* const* d_in, const int* in_sizes, int n_in,
                              void* d_out, int out_size)
{
    const float *x = nullptr, *Wqkv = nullptr, *bqkv = nullptr, *w1 = nullptr,
                *w2 = nullptr, *w3 = nullptr, *Wproj = nullptr, *bproj = nullptr;
    for (int i = 0; i < n_in; i++) {
        const int s = in_sizes[i];
        const float* p = (const float*)d_in[i];
        if      (s == B_*N_*C_)   x = p;
        else if (s == C_*QC)      Wqkv = p;
        else if (s == QC)         bqkv = p;
        else if (s == NH*HD_*HD_) { if (!w1) w1 = p; else w2 = p; }
        else if (s == 64*9)       w3 = p;
        else if (s == XC*C_)      Wproj = p;
        else if (s == C_)         bproj = p;
    }

    __half *qkvh, *xh, *xch, *wqh, *wph;
    cudaGetSymbolAddress((void**)&qkvh, g_qkvh);
    cudaGetSymbolAddress((void**)&xh,  g_xh);
    cudaGetSymbolAddress((void**)&xch, g_xch);
    cudaGetSymbolAddress((void**)&wqh, g_wqh);
    cudaGetSymbolAddress((void**)&wph, g_wph);

    cudaFuncSetAttribute(ttt_grad_kernel,
        cudaFuncAttributeMaxDynamicSharedMemorySize, TG_SMEM);
    cudaFuncSetAttribute(ttt_fwd_kernel,
        cudaFuncAttributeMaxDynamicSharedMemorySize, TF_SMEM);
    cudaFuncSetAttribute(tc_gemm,
        cudaFuncAttributeMaxDynamicSharedMemorySize, TCG_SMEM);

    // 1. convert x, transpose weights (plain fp16)
    convert_f16<<<(B_*N_*C_/4 + 255)/256, 256>>>(x, xh, B_*N_*C_/4);
    transpose_f16<<<dim3(QC/32, C_/32), 256>>>(Wqkv, wqh, C_, QC);
    transpose_f16<<<dim3(C_/32, XC/32), 256>>>(Wproj, wph, XC, C_);

    // 2. qkv = x @ Wqkv + bqkv  -> fp16 output
    tc_gemm<<<dim3((QC + 127)/128, (B_*N_)/128), 128, TCG_SMEM>>>(
        xh, wqh, bqkv, qkvh, 1, QC, C_);

    // 3. TTT (HMMA) + conv gradients, reduce, update
    ttt_grad_kernel<<<dim3(8, NH, B_), 256, TG_SMEM>>>(w1, w2);
    conv_grad_kernel<<<B_ * 64, 256>>>(w3);
    conv_grad_reduce_kernel<<<1, 576>>>();
    reduce_gw_stage1<<<192, 256>>>();
    reduce_gw_stage2<<<24, 256>>>();
    update_w_kernel<<<(98880 + 255)/256, 256>>>(w1, w2, w3);

    // 4. post-update forward
    ttt_fwd_kernel<<<dim3(8, NH, B_), 256, TF_SMEM>>>();
    conv_fwd_kernel<<<B_ * 64, 256>>>();

    // 5. proj GEMM -> fp32 d_out
    tc_gemm<<<dim3(C_/128, (B_*N_)/128), 128, TCG_SMEM>>>(
        xch, wph, bproj, d_out, 0, C_, XC);
}